// round 1
// baseline (speedup 1.0000x reference)
#include <cuda_runtime.h>
#include <math.h>

#define B_   2
#define S_   512
#define P_   64
#define T_   576
#define D_   1024
#define L_   4
#define DI_  2048
#define DS_  16
#define DR_  64
#define PCD_ 768
#define M_   (B_*T_)   // 1152

// ---------------- scratch (static device memory; no allocation) ----------------
__device__ float g_h   [M_*D_];       // residual stream
__device__ float g_xn  [M_*D_];       // rmsnorm output
__device__ float g_xz  [M_*2*DI_];    // in_proj output (xi | z)
__device__ float g_xi  [M_*DI_];      // conv+silu output
__device__ float g_dt  [M_*DI_];      // softplus(dt)
__device__ float g_y   [M_*DI_];      // scan output (gated)
__device__ float g_xdbl[M_*96];       // x_proj output (dt_r | B | C)
__device__ float g_p1  [128*D_];
__device__ float g_p2  [128*D_];

// ---------------- helpers ----------------
__device__ __forceinline__ float siluf(float x) { return x / (1.f + __expf(-x)); }
__device__ __forceinline__ float softplusf(float x) {
    return x > 20.f ? x : log1pf(__expf(x));
}

// ---------------- generic tiled fp32 GEMM ----------------
// C[M,N] (= or += or atomicAdd) A[M,K(lda)] * B^T (BT: B is [N,K]) or B [K,N]
// ACT: 0 none, 1 silu, 2 softplus(v + bias[n])
template<int BM, int BN, int BK, int TM, int TN, bool BT, bool ACC, bool SPLITK, int ACT>
__launch_bounds__((BM/TM)*(BN/TN), 2)
__global__ void gemm_k(const float* __restrict__ Ap, int lda,
                       const float* __restrict__ Bp,
                       const float* __restrict__ bias,
                       float* __restrict__ Cp,
                       int M, int N, int K) {
    constexpr int THREADS = (BM/TM)*(BN/TN);
    __shared__ float As[BK][BM];
    __shared__ float Bs[BK][BN];
    const int tid = threadIdx.x;
    const int tx  = tid % (BN/TN);
    const int ty  = tid / (BN/TN);
    const int m0  = blockIdx.x * BM;
    const int n0  = blockIdx.y * BN;
    int kBeg = 0, kEnd = K;
    if (SPLITK) { int kl = K / gridDim.z; kBeg = blockIdx.z * kl; kEnd = kBeg + kl; }

    float acc[TM][TN];
    #pragma unroll
    for (int i = 0; i < TM; i++)
        #pragma unroll
        for (int j = 0; j < TN; j++) acc[i][j] = 0.f;

    for (int k0 = kBeg; k0 < kEnd; k0 += BK) {
        // load A tile (transposed into As[k][m])
        #pragma unroll
        for (int i = tid; i < BM*BK/4; i += THREADS) {
            int row = i / (BK/4);
            int kc  = (i % (BK/4)) * 4;
            float4 v = make_float4(0.f,0.f,0.f,0.f);
            if (m0 + row < M)
                v = *(const float4*)(Ap + (size_t)(m0+row)*lda + k0 + kc);
            As[kc+0][row] = v.x; As[kc+1][row] = v.y;
            As[kc+2][row] = v.z; As[kc+3][row] = v.w;
        }
        // load B tile
        if (BT) {
            #pragma unroll
            for (int i = tid; i < BN*BK/4; i += THREADS) {
                int row = i / (BK/4);
                int kc  = (i % (BK/4)) * 4;
                float4 v = make_float4(0.f,0.f,0.f,0.f);
                if (n0 + row < N)
                    v = *(const float4*)(Bp + (size_t)(n0+row)*K + k0 + kc);
                Bs[kc+0][row] = v.x; Bs[kc+1][row] = v.y;
                Bs[kc+2][row] = v.z; Bs[kc+3][row] = v.w;
            }
        } else {
            #pragma unroll
            for (int i = tid; i < BK*BN/4; i += THREADS) {
                int kr = i / (BN/4);
                int nc = (i % (BN/4)) * 4;
                float4 v = make_float4(0.f,0.f,0.f,0.f);
                if (n0 + nc < N)
                    v = *(const float4*)(Bp + (size_t)(k0+kr)*N + n0 + nc);
                *(float4*)&Bs[kr][nc] = v;
            }
        }
        __syncthreads();

        #pragma unroll
        for (int kk = 0; kk < BK; kk++) {
            float a[TM], b[TN];
            #pragma unroll
            for (int i = 0; i < TM; i += 4)
                *(float4*)&a[i] = *(const float4*)&As[kk][ty*TM + i];
            #pragma unroll
            for (int j = 0; j < TN; j += 4)
                *(float4*)&b[j] = *(const float4*)&Bs[kk][tx*TN + j];
            #pragma unroll
            for (int i = 0; i < TM; i++)
                #pragma unroll
                for (int j = 0; j < TN; j++)
                    acc[i][j] = fmaf(a[i], b[j], acc[i][j]);
        }
        __syncthreads();
    }

    #pragma unroll
    for (int i = 0; i < TM; i++) {
        int m = m0 + ty*TM + i;
        if (m >= M) continue;
        #pragma unroll
        for (int j = 0; j < TN; j++) {
            int n = n0 + tx*TN + j;
            if (n >= N) continue;
            float v = acc[i][j];
            if (ACT == 1) v = siluf(v);
            if (ACT == 2) v = softplusf(v + bias[n]);
            size_t idx = (size_t)m*N + n;
            if (SPLITK)      atomicAdd(&Cp[idx], v);
            else if (ACC)    Cp[idx] += v;
            else             Cp[idx]  = v;
        }
    }
}

// ---------------- small utility kernels ----------------
__global__ void zero_kernel(float* __restrict__ p, int n) {
    int i = blockIdx.x * blockDim.x + threadIdx.x;
    if (i < n) p[i] = 0.f;
}

__global__ void silu_kernel(float* __restrict__ p, int n) {
    int i = blockIdx.x * blockDim.x + threadIdx.x;
    if (i < n) p[i] = siluf(p[i]);
}

__global__ void build_h_kernel(const float* __restrict__ p,
                               const float* __restrict__ x,
                               float* __restrict__ h) {
    int idx = blockIdx.x * blockDim.x + threadIdx.x;
    if (idx >= M_*D_) return;
    int d = idx % D_;
    int m = idx / D_;
    int b = m / T_;
    int t = m % T_;
    h[idx] = (t < P_) ? p[(size_t)(b*P_ + t)*D_ + d]
                      : x[(size_t)(b*S_ + (t - P_))*D_ + d];
}

__global__ void rmsnorm_kernel(const float* __restrict__ in,
                               const float* __restrict__ w,
                               float* __restrict__ out) {
    int row = blockIdx.x;
    int tid = threadIdx.x;                 // 256 threads, 4 floats each
    const float4* r = (const float4*)(in + (size_t)row*D_);
    float4 x4 = r[tid];
    float s = x4.x*x4.x + x4.y*x4.y + x4.z*x4.z + x4.w*x4.w;
    #pragma unroll
    for (int o = 16; o; o >>= 1) s += __shfl_xor_sync(0xffffffffu, s, o);
    __shared__ float ws[8];
    __shared__ float scale_s;
    if ((tid & 31) == 0) ws[tid >> 5] = s;
    __syncthreads();
    if (tid == 0) {
        float t = 0.f;
        #pragma unroll
        for (int i = 0; i < 8; i++) t += ws[i];
        scale_s = rsqrtf(t / (float)D_ + 1e-5f);
    }
    __syncthreads();
    float sc = scale_s;
    float4 wv = ((const float4*)w)[tid];
    float4 o4 = make_float4(x4.x*sc*wv.x, x4.y*sc*wv.y, x4.z*sc*wv.z, x4.w*sc*wv.w);
    ((float4*)(out + (size_t)row*D_))[tid] = o4;
}

__global__ void final_kernel(const float* __restrict__ hin,
                             const float* __restrict__ w,
                             float* __restrict__ out) {
    int row = blockIdx.x;                  // 0..B*S-1
    int b = row >> 9;                      // /512
    int t = row & 511;
    int hrow = b*T_ + P_ + t;
    int tid = threadIdx.x;
    const float4* r = (const float4*)(hin + (size_t)hrow*D_);
    float4 x4 = r[tid];
    float s = x4.x*x4.x + x4.y*x4.y + x4.z*x4.z + x4.w*x4.w;
    #pragma unroll
    for (int o = 16; o; o >>= 1) s += __shfl_xor_sync(0xffffffffu, s, o);
    __shared__ float ws[8];
    __shared__ float scale_s;
    if ((tid & 31) == 0) ws[tid >> 5] = s;
    __syncthreads();
    if (tid == 0) {
        float tt = 0.f;
        #pragma unroll
        for (int i = 0; i < 8; i++) tt += ws[i];
        scale_s = rsqrtf(tt / (float)D_ + 1e-5f);
    }
    __syncthreads();
    float sc = scale_s;
    float4 wv = ((const float4*)w)[tid];
    float4 o4 = make_float4(x4.x*sc*wv.x, x4.y*sc*wv.y, x4.z*sc*wv.z, x4.w*sc*wv.w);
    ((float4*)(out + (size_t)row*D_))[tid] = o4;
}

// depthwise causal conv (DC=4) + silu
__global__ void conv_silu_kernel(const float* __restrict__ xz,
                                 const float* __restrict__ cw,
                                 const float* __restrict__ cb,
                                 float* __restrict__ xi) {
    int idx = blockIdx.x * blockDim.x + threadIdx.x;
    if (idx >= M_*DI_) return;
    int e = idx % DI_;
    int m = idx / DI_;
    int t = m % T_;
    float4 w4 = ((const float4*)cw)[e];
    float wj[4] = {w4.x, w4.y, w4.z, w4.w};
    float acc = cb[e];
    #pragma unroll
    for (int j = 0; j < 4; j++) {
        int tt = t - 3 + j;
        if (tt >= 0)
            acc = fmaf(xz[(size_t)(m - 3 + j)*(2*DI_) + e], wj[j], acc);
    }
    xi[(size_t)m*DI_ + e] = siluf(acc);
}

// selective scan: warp = 2 channels x 16 states; sequential over T.
__global__ void scan_kernel(const float* __restrict__ xz,
                            const float* __restrict__ xi,
                            const float* __restrict__ xdbl,
                            const float* __restrict__ dt,
                            const float* __restrict__ A_log,
                            const float* __restrict__ Dp,
                            float* __restrict__ y) {
    int lane = threadIdx.x & 31;
    int warp = threadIdx.x >> 5;
    int pair = blockIdx.x * 4 + warp;        // 0 .. B*DI/2-1
    int b = pair >> 10;                       // / (DI/2)
    int e = ((pair & 1023) << 1) + (lane >> 4);
    int s = lane & 15;

    float A  = -expf(A_log[(size_t)e*DS_ + s]);
    float Dv = Dp[e];
    float h  = 0.f;
    int m0 = b * T_;

    const float* dt_p = dt   + (size_t)m0*DI_ + e;
    const float* xi_p = xi   + (size_t)m0*DI_ + e;
    const float* z_p  = xz   + (size_t)m0*(2*DI_) + DI_ + e;
    const float* bc_p = xdbl + (size_t)m0*96 + DR_ + s;   // B at +0, C at +16
    float*       y_p  = y    + (size_t)m0*DI_ + e;

    // software pipeline: prefetch t+1 while computing t
    float dtv = dt_p[0], xiv = xi_p[0], Bv = bc_p[0], Cv = bc_p[16], zv = z_p[0];
    for (int t = 0; t < T_; t++) {
        float n_dt = 0.f, n_xi = 0.f, n_B = 0.f, n_C = 0.f, n_z = 0.f;
        if (t + 1 < T_) {
            n_dt = dt_p[(size_t)(t+1)*DI_];
            n_xi = xi_p[(size_t)(t+1)*DI_];
            n_B  = bc_p[(size_t)(t+1)*96];
            n_C  = bc_p[(size_t)(t+1)*96 + 16];
            n_z  = z_p [(size_t)(t+1)*(2*DI_)];
        }
        float dA = __expf(dtv * A);
        h = fmaf(dA, h, dtv * Bv * xiv);
        float p = h * Cv;
        p += __shfl_xor_sync(0xffffffffu, p, 8);
        p += __shfl_xor_sync(0xffffffffu, p, 4);
        p += __shfl_xor_sync(0xffffffffu, p, 2);
        p += __shfl_xor_sync(0xffffffffu, p, 1);
        if (s == 0)
            y_p[(size_t)t*DI_] = (p + xiv * Dv) * siluf(zv);
        dtv = n_dt; xiv = n_xi; Bv = n_B; Cv = n_C; zv = n_z;
    }
}

// ---------------- host orchestration ----------------
extern "C" void kernel_launch(void* const* d_in, const int* in_sizes, int n_in,
                              void* d_out, int out_size) {
    (void)in_sizes; (void)n_in; (void)out_size;
    const float* x      = (const float*)d_in[0];
    const float* pc     = (const float*)d_in[1];
    const float* w1     = (const float*)d_in[2];
    const float* w2     = (const float*)d_in[3];
    const float* norm_w = (const float*)d_in[4];
    const float* ipw    = (const float*)d_in[5];
    const float* cw     = (const float*)d_in[6];
    const float* cb     = (const float*)d_in[7];
    const float* xpw    = (const float*)d_in[8];
    const float* dtw    = (const float*)d_in[9];
    const float* dtb    = (const float*)d_in[10];
    const float* A_log  = (const float*)d_in[11];
    const float* Dparam = (const float*)d_in[12];
    const float* opw    = (const float*)d_in[13];
    const float* fnw    = (const float*)d_in[14];

    float *h, *xn, *xzp, *xip, *dtp, *yp, *xdblp, *p1, *p2;
    cudaGetSymbolAddress((void**)&h,     g_h);
    cudaGetSymbolAddress((void**)&xn,    g_xn);
    cudaGetSymbolAddress((void**)&xzp,   g_xz);
    cudaGetSymbolAddress((void**)&xip,   g_xi);
    cudaGetSymbolAddress((void**)&dtp,   g_dt);
    cudaGetSymbolAddress((void**)&yp,    g_y);
    cudaGetSymbolAddress((void**)&xdblp, g_xdbl);
    cudaGetSymbolAddress((void**)&p1,    g_p1);
    cudaGetSymbolAddress((void**)&p2,    g_p2);

    // ---- prepend MLP: p = silu(pc @ w1) @ w2 ----
    zero_kernel<<<(128*D_+255)/256, 256>>>(p1, 128*D_);
    gemm_k<64,64,16,4,4,false,false,true,0><<<dim3(2,16,3), 256>>>(
        pc, PCD_, w1, nullptr, p1, 128, D_, PCD_);
    silu_kernel<<<(128*D_+255)/256, 256>>>(p1, 128*D_);
    zero_kernel<<<(128*D_+255)/256, 256>>>(p2, 128*D_);
    gemm_k<64,64,16,4,4,false,false,true,0><<<dim3(2,16,4), 256>>>(
        p1, D_, w2, nullptr, p2, 128, D_, D_);
    build_h_kernel<<<(M_*D_+255)/256, 256>>>(p2, x, h);

    // ---- 4 mamba layers ----
    for (int l = 0; l < L_; l++) {
        rmsnorm_kernel<<<M_, 256>>>(h, norm_w + (size_t)l*D_, xn);

        // xz = xn @ in_proj_w^T  [1152,1024]x[4096,1024]^T
        gemm_k<128,128,16,8,8,true,false,false,0><<<dim3(9,32), 256>>>(
            xn, D_, ipw + (size_t)l*2*DI_*D_, nullptr, xzp, M_, 2*DI_, D_);

        conv_silu_kernel<<<(M_*DI_+255)/256, 256>>>(
            xzp, cw + (size_t)l*DI_*4, cb + (size_t)l*DI_, xip);

        // xdbl = xi @ x_proj_w^T  [1152,2048]x[96,2048]^T (split-K)
        zero_kernel<<<(M_*96+255)/256, 256>>>(xdblp, M_*96);
        gemm_k<128,128,16,8,8,true,false,true,0><<<dim3(9,1,16), 256>>>(
            xip, DI_, xpw + (size_t)l*96*DI_, nullptr, xdblp, M_, 96, DI_);

        // dt = softplus(xdbl[:, :64] @ dt_proj_w^T + b)  [1152,64]x[2048,64]^T
        gemm_k<128,128,16,8,8,true,false,false,2><<<dim3(9,16), 256>>>(
            xdblp, 96, dtw + (size_t)l*DI_*DR_, dtb + (size_t)l*DI_, dtp,
            M_, DI_, DR_);

        // selective scan + gate
        scan_kernel<<<(B_*DI_/2)/4, 128>>>(
            xzp, xip, xdblp, dtp,
            A_log + (size_t)l*DI_*DS_, Dparam + (size_t)l*DI_, yp);

        // h += y @ out_proj_w^T  [1152,2048]x[1024,2048]^T
        gemm_k<128,64,16,8,4,true,true,false,0><<<dim3(9,16), 256>>>(
            yp, DI_, opw + (size_t)l*D_*DI_, nullptr, h, M_, D_, DI_);
    }

    // ---- final rmsnorm + slice ----
    final_kernel<<<B_*S_, 256>>>(h, fnw, (float*)d_out);
}

// round 2
// speedup vs baseline: 1.5395x; 1.5395x over previous
#include <cuda_runtime.h>
#include <cuda_bf16.h>
#include <math.h>
#include <stdint.h>

#define B_   2
#define S_   512
#define P_   64
#define T_   576
#define D_   1024
#define L_   4
#define DI_  2048
#define DS_  16
#define DR_  64
#define PCD_ 768
#define M_   (B_*T_)   // 1152

// ---------------- static scratch ----------------
__device__ float g_h   [M_*D_];
__device__ float g_xz  [M_*2*DI_];
__device__ float g_xi  [M_*DI_];
__device__ float g_dt  [M_*DI_];
__device__ float g_xdbl[M_*96];
__device__ float g_p1  [128*D_];
__device__ float g_p2  [128*D_];

__device__ __align__(16) __nv_bfloat16 g_xn_h [M_*D_],  g_xn_l [M_*D_];
__device__ __align__(16) __nv_bfloat16 g_xi_h [M_*DI_], g_xi_l [M_*DI_];
__device__ __align__(16) __nv_bfloat16 g_y_h  [M_*DI_], g_y_l  [M_*DI_];
__device__ __align__(16) __nv_bfloat16 g_dtr_h[M_*DR_], g_dtr_l[M_*DR_];

__device__ __align__(16) __nv_bfloat16 g_ipw_h[L_*2*DI_*D_], g_ipw_l[L_*2*DI_*D_];
__device__ __align__(16) __nv_bfloat16 g_opw_h[L_*D_*DI_],   g_opw_l[L_*D_*DI_];
__device__ __align__(16) __nv_bfloat16 g_xpw_h[L_*128*DI_],  g_xpw_l[L_*128*DI_];  // N padded 96->128
__device__ __align__(16) __nv_bfloat16 g_dtw_h[L_*DI_*DR_],  g_dtw_l[L_*DI_*DR_];

// ---------------- helpers ----------------
__device__ __forceinline__ float siluf(float x) { return x / (1.f + __expf(-x)); }
__device__ __forceinline__ float softplusf(float x) {
    return x > 20.f ? x : log1pf(__expf(x));
}
__device__ __forceinline__ void split_write(float x, __nv_bfloat16* h, __nv_bfloat16* l) {
    __nv_bfloat16 hv = __float2bfloat16(x);
    *h = hv;
    *l = __float2bfloat16(x - __bfloat162float(hv));
}

// ---------------- bf16-split tensor-core GEMM ----------------
// C[M x NC] (+)= A[M x K] * B[N x K]^T   where A ~ Ah+Al, B ~ Bh+Bl (bf16 splits)
// BM=64, BN=128, BK=32, 128 threads (4 warps 2x2), warp tile 32x64, m16n8k16.
// EPI: 0 = store, 1 = atomicAdd (split-K / accumulate), 2 = softplus(v+bias[n]) store
__device__ __forceinline__ void mma16816(float* c, const uint32_t* a, const uint32_t* b) {
    asm volatile(
        "mma.sync.aligned.m16n8k16.row.col.f32.bf16.bf16.f32 "
        "{%0,%1,%2,%3}, {%4,%5,%6,%7}, {%8,%9}, {%0,%1,%2,%3};"
        : "+f"(c[0]), "+f"(c[1]), "+f"(c[2]), "+f"(c[3])
        : "r"(a[0]), "r"(a[1]), "r"(a[2]), "r"(a[3]), "r"(b[0]), "r"(b[1]));
}

template<int EPI>
__global__ void __launch_bounds__(128, 3)
mma_gemm(const __nv_bfloat16* __restrict__ Ah, const __nv_bfloat16* __restrict__ Al,
         const __nv_bfloat16* __restrict__ Bh, const __nv_bfloat16* __restrict__ Bl,
         const float* __restrict__ bias, float* __restrict__ C,
         int K, int NC, int ldc)
{
    __shared__ __align__(16) __nv_bfloat16 AsH[64][40],  AsL[64][40];
    __shared__ __align__(16) __nv_bfloat16 BsH[128][40], BsL[128][40];

    const int tid  = threadIdx.x;
    const int lane = tid & 31;
    const int wid  = tid >> 5;
    const int wm   = wid >> 1;           // 0..1
    const int wn   = wid & 1;            // 0..1
    const int m0   = blockIdx.x * 64;
    const int n0   = blockIdx.y * 128;
    const int kPer = K / gridDim.z;
    const int kBeg = blockIdx.z * kPer;

    float acc[2][8][4];
    #pragma unroll
    for (int mi = 0; mi < 2; mi++)
        #pragma unroll
        for (int ni = 0; ni < 8; ni++)
            #pragma unroll
            for (int q = 0; q < 4; q++) acc[mi][ni][q] = 0.f;

    const int r4 = tid >> 2;             // 0..31
    const int c8 = (tid & 3) * 8;        // 0,8,16,24

    for (int k0 = kBeg; k0 < kBeg + kPer; k0 += 32) {
        #pragma unroll
        for (int i = 0; i < 2; i++) {
            int r = r4 + i * 32;
            size_t g = (size_t)(m0 + r) * K + k0 + c8;
            *(uint4*)&AsH[r][c8] = *(const uint4*)(Ah + g);
            *(uint4*)&AsL[r][c8] = *(const uint4*)(Al + g);
        }
        #pragma unroll
        for (int i = 0; i < 4; i++) {
            int r = r4 + i * 32;
            size_t g = (size_t)(n0 + r) * K + k0 + c8;
            *(uint4*)&BsH[r][c8] = *(const uint4*)(Bh + g);
            *(uint4*)&BsL[r][c8] = *(const uint4*)(Bl + g);
        }
        __syncthreads();

        #pragma unroll
        for (int kk = 0; kk < 32; kk += 16) {
            uint32_t aH[2][4], aL[2][4], bH[8][2], bL[8][2];
            const int ac = kk + (lane & 3) * 2;
            #pragma unroll
            for (int mi = 0; mi < 2; mi++) {
                int ar = wm * 32 + mi * 16 + (lane >> 2);
                aH[mi][0] = *(const uint32_t*)&AsH[ar    ][ac    ];
                aH[mi][1] = *(const uint32_t*)&AsH[ar + 8][ac    ];
                aH[mi][2] = *(const uint32_t*)&AsH[ar    ][ac + 8];
                aH[mi][3] = *(const uint32_t*)&AsH[ar + 8][ac + 8];
                aL[mi][0] = *(const uint32_t*)&AsL[ar    ][ac    ];
                aL[mi][1] = *(const uint32_t*)&AsL[ar + 8][ac    ];
                aL[mi][2] = *(const uint32_t*)&AsL[ar    ][ac + 8];
                aL[mi][3] = *(const uint32_t*)&AsL[ar + 8][ac + 8];
            }
            #pragma unroll
            for (int ni = 0; ni < 8; ni++) {
                int br = wn * 64 + ni * 8 + (lane >> 2);
                bH[ni][0] = *(const uint32_t*)&BsH[br][ac    ];
                bH[ni][1] = *(const uint32_t*)&BsH[br][ac + 8];
                bL[ni][0] = *(const uint32_t*)&BsL[br][ac    ];
                bL[ni][1] = *(const uint32_t*)&BsL[br][ac + 8];
            }
            // 3 passes: hh, hl, lh (acc reuse distance = 16 mma -> no RAW stall)
            #pragma unroll
            for (int mi = 0; mi < 2; mi++)
                #pragma unroll
                for (int ni = 0; ni < 8; ni++) mma16816(acc[mi][ni], aH[mi], bH[ni]);
            #pragma unroll
            for (int mi = 0; mi < 2; mi++)
                #pragma unroll
                for (int ni = 0; ni < 8; ni++) mma16816(acc[mi][ni], aH[mi], bL[ni]);
            #pragma unroll
            for (int mi = 0; mi < 2; mi++)
                #pragma unroll
                for (int ni = 0; ni < 8; ni++) mma16816(acc[mi][ni], aL[mi], bH[ni]);
        }
        __syncthreads();
    }

    // epilogue
    #pragma unroll
    for (int mi = 0; mi < 2; mi++) {
        #pragma unroll
        for (int ni = 0; ni < 8; ni++) {
            int r  = m0 + wm * 32 + mi * 16 + (lane >> 2);
            int cc = n0 + wn * 64 + ni * 8 + (lane & 3) * 2;
            #pragma unroll
            for (int half = 0; half < 2; half++) {
                int rr = r + half * 8;
                float v0 = acc[mi][ni][half * 2];
                float v1 = acc[mi][ni][half * 2 + 1];
                if (EPI == 2) {
                    v0 = softplusf(v0 + bias[cc]);
                    v1 = softplusf(v1 + bias[cc + 1]);
                }
                if (cc < NC) {
                    size_t o = (size_t)rr * ldc + cc;
                    if (EPI == 1) {
                        atomicAdd(&C[o], v0);
                        if (cc + 1 < NC) atomicAdd(&C[o + 1], v1);
                    } else {
                        C[o] = v0;
                        if (cc + 1 < NC) C[o + 1] = v1;
                    }
                }
            }
        }
    }
}

// ---------------- fp32 split-K GEMM (prepend MLP only) ----------------
template<int BM, int BN, int BK, int TM, int TN>
__launch_bounds__((BM/TM)*(BN/TN), 2)
__global__ void gemm_f32(const float* __restrict__ Ap, int lda,
                         const float* __restrict__ Bp,
                         float* __restrict__ Cp,
                         int M, int N, int K) {
    constexpr int THREADS = (BM/TM)*(BN/TN);
    __shared__ float As[BK][BM];
    __shared__ float Bs[BK][BN];
    const int tid = threadIdx.x;
    const int tx  = tid % (BN/TN);
    const int ty  = tid / (BN/TN);
    const int m0  = blockIdx.x * BM;
    const int n0  = blockIdx.y * BN;
    int kl = K / gridDim.z;
    int kBeg = blockIdx.z * kl, kEnd = kBeg + kl;

    float acc[TM][TN];
    #pragma unroll
    for (int i = 0; i < TM; i++)
        #pragma unroll
        for (int j = 0; j < TN; j++) acc[i][j] = 0.f;

    for (int k0 = kBeg; k0 < kEnd; k0 += BK) {
        #pragma unroll
        for (int i = tid; i < BM*BK/4; i += THREADS) {
            int row = i / (BK/4);
            int kc  = (i % (BK/4)) * 4;
            float4 v = make_float4(0.f,0.f,0.f,0.f);
            if (m0 + row < M)
                v = *(const float4*)(Ap + (size_t)(m0+row)*lda + k0 + kc);
            As[kc+0][row] = v.x; As[kc+1][row] = v.y;
            As[kc+2][row] = v.z; As[kc+3][row] = v.w;
        }
        #pragma unroll
        for (int i = tid; i < BK*BN/4; i += THREADS) {
            int kr = i / (BN/4);
            int nc = (i % (BN/4)) * 4;
            float4 v = *(const float4*)(Bp + (size_t)(k0+kr)*N + n0 + nc);
            *(float4*)&Bs[kr][nc] = v;
        }
        __syncthreads();
        #pragma unroll
        for (int kk = 0; kk < BK; kk++) {
            float a[TM], b[TN];
            #pragma unroll
            for (int i = 0; i < TM; i += 4)
                *(float4*)&a[i] = *(const float4*)&As[kk][ty*TM + i];
            #pragma unroll
            for (int j = 0; j < TN; j += 4)
                *(float4*)&b[j] = *(const float4*)&Bs[kk][tx*TN + j];
            #pragma unroll
            for (int i = 0; i < TM; i++)
                #pragma unroll
                for (int j = 0; j < TN; j++)
                    acc[i][j] = fmaf(a[i], b[j], acc[i][j]);
        }
        __syncthreads();
    }
    #pragma unroll
    for (int i = 0; i < TM; i++) {
        int m = m0 + ty*TM + i;
        if (m >= M) continue;
        #pragma unroll
        for (int j = 0; j < TN; j++) {
            int n = n0 + tx*TN + j;
            atomicAdd(&Cp[(size_t)m*N + n], acc[i][j]);
        }
    }
}

// ---------------- split / prep kernels ----------------
__global__ void split2_kernel(const float* __restrict__ in,
                              __nv_bfloat16* __restrict__ h,
                              __nv_bfloat16* __restrict__ l, int n) {
    int i = blockIdx.x * 256 + threadIdx.x;
    if (i >= n) return;
    split_write(in[i], h + i, l + i);
}

// x_proj weights: [L][96][DI] -> padded [L][128][DI]
__global__ void split_xpw_kernel(const float* __restrict__ in,
                                 __nv_bfloat16* __restrict__ h,
                                 __nv_bfloat16* __restrict__ l) {
    int i = blockIdx.x * 256 + threadIdx.x;
    if (i >= L_ * 128 * DI_) return;
    int k    = i % DI_;
    int nrow = (i / DI_) % 128;
    int lay  = i / (128 * DI_);
    float x = (nrow < 96) ? in[(size_t)lay * 96 * DI_ + (size_t)nrow * DI_ + k] : 0.f;
    split_write(x, h + i, l + i);
}

// dt_rank columns of xdbl -> contiguous [M][64] split
__global__ void split_dtr_kernel(const float* __restrict__ xdbl,
                                 __nv_bfloat16* __restrict__ h,
                                 __nv_bfloat16* __restrict__ l) {
    int i = blockIdx.x * 256 + threadIdx.x;
    if (i >= M_ * DR_) return;
    int m = i / DR_, c = i % DR_;
    split_write(xdbl[(size_t)m * 96 + c], h + i, l + i);
}

__global__ void zero_kernel(float* __restrict__ p, int n) {
    int i = blockIdx.x * blockDim.x + threadIdx.x;
    if (i < n) p[i] = 0.f;
}

__global__ void silu_kernel(float* __restrict__ p, int n) {
    int i = blockIdx.x * blockDim.x + threadIdx.x;
    if (i < n) p[i] = siluf(p[i]);
}

__global__ void build_h_kernel(const float* __restrict__ p,
                               const float* __restrict__ x,
                               float* __restrict__ h) {
    int idx = blockIdx.x * blockDim.x + threadIdx.x;
    if (idx >= M_*D_) return;
    int d = idx % D_;
    int m = idx / D_;
    int b = m / T_;
    int t = m % T_;
    h[idx] = (t < P_) ? p[(size_t)(b*P_ + t)*D_ + d]
                      : x[(size_t)(b*S_ + (t - P_))*D_ + d];
}

// rmsnorm -> bf16 hi/lo splits
__global__ void rmsnorm_split_kernel(const float* __restrict__ in,
                                     const float* __restrict__ w,
                                     __nv_bfloat16* __restrict__ oh,
                                     __nv_bfloat16* __restrict__ ol) {
    int row = blockIdx.x;
    int tid = threadIdx.x;                 // 256 threads, 4 floats each
    const float4* r = (const float4*)(in + (size_t)row*D_);
    float4 x4 = r[tid];
    float s = x4.x*x4.x + x4.y*x4.y + x4.z*x4.z + x4.w*x4.w;
    #pragma unroll
    for (int o = 16; o; o >>= 1) s += __shfl_xor_sync(0xffffffffu, s, o);
    __shared__ float ws[8];
    __shared__ float scale_s;
    if ((tid & 31) == 0) ws[tid >> 5] = s;
    __syncthreads();
    if (tid == 0) {
        float t = 0.f;
        #pragma unroll
        for (int i = 0; i < 8; i++) t += ws[i];
        scale_s = rsqrtf(t / (float)D_ + 1e-5f);
    }
    __syncthreads();
    float sc = scale_s;
    float4 wv = ((const float4*)w)[tid];
    float v[4] = { x4.x*sc*wv.x, x4.y*sc*wv.y, x4.z*sc*wv.z, x4.w*sc*wv.w };
    size_t base = (size_t)row*D_ + tid*4;
    #pragma unroll
    for (int q = 0; q < 4; q++)
        split_write(v[q], oh + base + q, ol + base + q);
}

__global__ void final_kernel(const float* __restrict__ hin,
                             const float* __restrict__ w,
                             float* __restrict__ out) {
    int row = blockIdx.x;                  // 0..B*S-1
    int b = row >> 9;
    int t = row & 511;
    int hrow = b*T_ + P_ + t;
    int tid = threadIdx.x;
    const float4* r = (const float4*)(hin + (size_t)hrow*D_);
    float4 x4 = r[tid];
    float s = x4.x*x4.x + x4.y*x4.y + x4.z*x4.z + x4.w*x4.w;
    #pragma unroll
    for (int o = 16; o; o >>= 1) s += __shfl_xor_sync(0xffffffffu, s, o);
    __shared__ float ws[8];
    __shared__ float scale_s;
    if ((tid & 31) == 0) ws[tid >> 5] = s;
    __syncthreads();
    if (tid == 0) {
        float tt = 0.f;
        #pragma unroll
        for (int i = 0; i < 8; i++) tt += ws[i];
        scale_s = rsqrtf(tt / (float)D_ + 1e-5f);
    }
    __syncthreads();
    float sc = scale_s;
    float4 wv = ((const float4*)w)[tid];
    float4 o4 = make_float4(x4.x*sc*wv.x, x4.y*sc*wv.y, x4.z*sc*wv.z, x4.w*sc*wv.w);
    ((float4*)(out + (size_t)row*D_))[tid] = o4;
}

// depthwise causal conv (DC=4) + silu, writes fp32 + bf16 splits
__global__ void conv_silu_kernel(const float* __restrict__ xz,
                                 const float* __restrict__ cw,
                                 const float* __restrict__ cb,
                                 float* __restrict__ xi,
                                 __nv_bfloat16* __restrict__ xih,
                                 __nv_bfloat16* __restrict__ xil) {
    int idx = blockIdx.x * blockDim.x + threadIdx.x;
    if (idx >= M_*DI_) return;
    int e = idx % DI_;
    int m = idx / DI_;
    int t = m % T_;
    float4 w4 = ((const float4*)cw)[e];
    float wj[4] = {w4.x, w4.y, w4.z, w4.w};
    float acc = cb[e];
    #pragma unroll
    for (int j = 0; j < 4; j++) {
        int tt = t - 3 + j;
        if (tt >= 0)
            acc = fmaf(xz[(size_t)(m - 3 + j)*(2*DI_) + e], wj[j], acc);
    }
    float v = siluf(acc);
    size_t o = (size_t)m*DI_ + e;
    xi[o] = v;
    split_write(v, xih + o, xil + o);
}

// selective scan: warp = 2 channels x 16 states; writes y bf16 splits.
__global__ void scan_kernel(const float* __restrict__ xz,
                            const float* __restrict__ xi,
                            const float* __restrict__ xdbl,
                            const float* __restrict__ dt,
                            const float* __restrict__ A_log,
                            const float* __restrict__ Dp,
                            __nv_bfloat16* __restrict__ yh,
                            __nv_bfloat16* __restrict__ yl) {
    int lane = threadIdx.x & 31;
    int warp = threadIdx.x >> 5;
    int pair = blockIdx.x * 4 + warp;        // 0 .. B*DI/2-1
    int b = pair >> 10;
    int e = ((pair & 1023) << 1) + (lane >> 4);
    int s = lane & 15;

    float A  = -expf(A_log[(size_t)e*DS_ + s]);
    float Dv = Dp[e];
    float h  = 0.f;
    int m0 = b * T_;

    const float* dt_p = dt   + (size_t)m0*DI_ + e;
    const float* xi_p = xi   + (size_t)m0*DI_ + e;
    const float* z_p  = xz   + (size_t)m0*(2*DI_) + DI_ + e;
    const float* bc_p = xdbl + (size_t)m0*96 + DR_ + s;
    size_t ybase = (size_t)m0*DI_ + e;

    float dtv = dt_p[0], xiv = xi_p[0], Bv = bc_p[0], Cv = bc_p[16], zv = z_p[0];
    for (int t = 0; t < T_; t++) {
        float n_dt = 0.f, n_xi = 0.f, n_B = 0.f, n_C = 0.f, n_z = 0.f;
        if (t + 1 < T_) {
            n_dt = dt_p[(size_t)(t+1)*DI_];
            n_xi = xi_p[(size_t)(t+1)*DI_];
            n_B  = bc_p[(size_t)(t+1)*96];
            n_C  = bc_p[(size_t)(t+1)*96 + 16];
            n_z  = z_p [(size_t)(t+1)*(2*DI_)];
        }
        float dA = __expf(dtv * A);
        h = fmaf(dA, h, dtv * Bv * xiv);
        float p = h * Cv;
        p += __shfl_xor_sync(0xffffffffu, p, 8);
        p += __shfl_xor_sync(0xffffffffu, p, 4);
        p += __shfl_xor_sync(0xffffffffu, p, 2);
        p += __shfl_xor_sync(0xffffffffu, p, 1);
        if (s == 0) {
            float val = (p + xiv * Dv) * siluf(zv);
            size_t o = ybase + (size_t)t*DI_;
            __nv_bfloat16 hv = __float2bfloat16(val);
            yh[o] = hv;
            yl[o] = __float2bfloat16(val - __bfloat162float(hv));
        }
        dtv = n_dt; xiv = n_xi; Bv = n_B; Cv = n_C; zv = n_z;
    }
}

// ---------------- host orchestration ----------------
extern "C" void kernel_launch(void* const* d_in, const int* in_sizes, int n_in,
                              void* d_out, int out_size) {
    (void)in_sizes; (void)n_in; (void)out_size;
    const float* x      = (const float*)d_in[0];
    const float* pc     = (const float*)d_in[1];
    const float* w1     = (const float*)d_in[2];
    const float* w2     = (const float*)d_in[3];
    const float* norm_w = (const float*)d_in[4];
    const float* ipw    = (const float*)d_in[5];
    const float* cw     = (const float*)d_in[6];
    const float* cb     = (const float*)d_in[7];
    const float* xpw    = (const float*)d_in[8];
    const float* dtw    = (const float*)d_in[9];
    const float* dtb    = (const float*)d_in[10];
    const float* A_log  = (const float*)d_in[11];
    const float* Dparam = (const float*)d_in[12];
    const float* opw    = (const float*)d_in[13];
    const float* fnw    = (const float*)d_in[14];

    float *h, *xzp, *xip, *dtp, *xdblp, *p1, *p2;
    cudaGetSymbolAddress((void**)&h,     g_h);
    cudaGetSymbolAddress((void**)&xzp,   g_xz);
    cudaGetSymbolAddress((void**)&xip,   g_xi);
    cudaGetSymbolAddress((void**)&dtp,   g_dt);
    cudaGetSymbolAddress((void**)&xdblp, g_xdbl);
    cudaGetSymbolAddress((void**)&p1,    g_p1);
    cudaGetSymbolAddress((void**)&p2,    g_p2);

    __nv_bfloat16 *xnh, *xnl, *xih, *xil, *yh, *yl, *dtrh, *dtrl;
    __nv_bfloat16 *ipwh, *ipwl, *opwh, *opwl, *xpwh, *xpwl, *dtwh, *dtwl;
    cudaGetSymbolAddress((void**)&xnh,  g_xn_h);  cudaGetSymbolAddress((void**)&xnl,  g_xn_l);
    cudaGetSymbolAddress((void**)&xih,  g_xi_h);  cudaGetSymbolAddress((void**)&xil,  g_xi_l);
    cudaGetSymbolAddress((void**)&yh,   g_y_h);   cudaGetSymbolAddress((void**)&yl,   g_y_l);
    cudaGetSymbolAddress((void**)&dtrh, g_dtr_h); cudaGetSymbolAddress((void**)&dtrl, g_dtr_l);
    cudaGetSymbolAddress((void**)&ipwh, g_ipw_h); cudaGetSymbolAddress((void**)&ipwl, g_ipw_l);
    cudaGetSymbolAddress((void**)&opwh, g_opw_h); cudaGetSymbolAddress((void**)&opwl, g_opw_l);
    cudaGetSymbolAddress((void**)&xpwh, g_xpw_h); cudaGetSymbolAddress((void**)&xpwl, g_xpw_l);
    cudaGetSymbolAddress((void**)&dtwh, g_dtw_h); cudaGetSymbolAddress((void**)&dtwl, g_dtw_l);

    // ---- weight splits (per-launch; pure bandwidth) ----
    {
        int n;
        n = L_*2*DI_*D_;  split2_kernel<<<(n+255)/256, 256>>>(ipw, ipwh, ipwl, n);
        n = L_*D_*DI_;    split2_kernel<<<(n+255)/256, 256>>>(opw, opwh, opwl, n);
        n = L_*DI_*DR_;   split2_kernel<<<(n+255)/256, 256>>>(dtw, dtwh, dtwl, n);
        n = L_*128*DI_;   split_xpw_kernel<<<(n+255)/256, 256>>>(xpw, xpwh, xpwl);
    }

    // ---- prepend MLP: p = silu(pc @ w1) @ w2 (fp32 split-K) ----
    zero_kernel<<<(128*D_+255)/256, 256>>>(p1, 128*D_);
    gemm_f32<64,64,16,4,4><<<dim3(2,16,3), 256>>>(pc, PCD_, w1, p1, 128, D_, PCD_);
    silu_kernel<<<(128*D_+255)/256, 256>>>(p1, 128*D_);
    zero_kernel<<<(128*D_+255)/256, 256>>>(p2, 128*D_);
    gemm_f32<64,64,16,4,4><<<dim3(2,16,4), 256>>>(p1, D_, w2, p2, 128, D_, D_);
    build_h_kernel<<<(M_*D_+255)/256, 256>>>(p2, x, h);

    // ---- 4 mamba layers ----
    for (int l = 0; l < L_; l++) {
        rmsnorm_split_kernel<<<M_, 256>>>(h, norm_w + (size_t)l*D_, xnh, xnl);

        // xz = xn @ in_proj_w^T   [1152,1024] x [4096,1024]^T
        mma_gemm<0><<<dim3(18, 32, 1), 128>>>(
            xnh, xnl, ipwh + (size_t)l*2*DI_*D_, ipwl + (size_t)l*2*DI_*D_,
            nullptr, xzp, D_, 2*DI_, 2*DI_);

        conv_silu_kernel<<<(M_*DI_+255)/256, 256>>>(
            xzp, cw + (size_t)l*DI_*4, cb + (size_t)l*DI_, xip, xih, xil);

        // xdbl = xi @ x_proj_w^T  [1152,2048] x [96,2048]^T (padded N=128, split-K=8)
        zero_kernel<<<(M_*96+255)/256, 256>>>(xdblp, M_*96);
        mma_gemm<1><<<dim3(18, 1, 8), 128>>>(
            xih, xil, xpwh + (size_t)l*128*DI_, xpwl + (size_t)l*128*DI_,
            nullptr, xdblp, DI_, 96, 96);

        split_dtr_kernel<<<(M_*DR_+255)/256, 256>>>(xdblp, dtrh, dtrl);

        // dt = softplus(dtr @ dt_proj_w^T + b)  [1152,64] x [2048,64]^T
        mma_gemm<2><<<dim3(18, 16, 1), 128>>>(
            dtrh, dtrl, dtwh + (size_t)l*DI_*DR_, dtwl + (size_t)l*DI_*DR_,
            dtb + (size_t)l*DI_, dtp, DR_, DI_, DI_);

        // selective scan + gate -> y splits
        scan_kernel<<<(B_*DI_/2)/4, 128>>>(
            xzp, xip, xdblp, dtp,
            A_log + (size_t)l*DI_*DS_, Dparam + (size_t)l*DI_, yh, yl);

        // h += y @ out_proj_w^T   [1152,2048] x [1024,2048]^T (split-K=2, atomic)
        mma_gemm<1><<<dim3(18, 8, 2), 128>>>(
            yh, yl, opwh + (size_t)l*D_*DI_, opwl + (size_t)l*D_*DI_,
            nullptr, h, DI_, D_, D_);
    }

    // ---- final rmsnorm + slice ----
    final_kernel<<<B_*S_, 256>>>(h, fnw, (float*)d_out);
}

// round 4
// speedup vs baseline: 1.9475x; 1.2650x over previous
#include <cuda_runtime.h>
#include <cuda_bf16.h>
#include <math.h>
#include <stdint.h>

#define B_   2
#define S_   512
#define P_   64
#define T_   576
#define D_   1024
#define L_   4
#define DI_  2048
#define DS_  16
#define DR_  64
#define PCD_ 768
#define M_   (B_*T_)   // 1152

// ---------------- static scratch ----------------
__device__ float g_h   [M_*D_];
__device__ float g_xz  [M_*2*DI_];
__device__ float g_xi  [M_*DI_];
__device__ float g_dt  [M_*DI_];
__device__ float g_xdbl[M_*96];
__device__ float g_p1  [128*D_];
__device__ float g_p2  [128*D_];

__device__ __align__(16) __nv_bfloat16 g_xn_h [M_*D_],  g_xn_l [M_*D_];
__device__ __align__(16) __nv_bfloat16 g_xi_h [M_*DI_], g_xi_l [M_*DI_];
__device__ __align__(16) __nv_bfloat16 g_y_h  [M_*DI_], g_y_l  [M_*DI_];
__device__ __align__(16) __nv_bfloat16 g_dtr_h[M_*DR_], g_dtr_l[M_*DR_];

__device__ __align__(16) __nv_bfloat16 g_ipw_h[L_*2*DI_*D_], g_ipw_l[L_*2*DI_*D_];
__device__ __align__(16) __nv_bfloat16 g_opw_h[L_*D_*DI_],   g_opw_l[L_*D_*DI_];
__device__ __align__(16) __nv_bfloat16 g_xpw_h[L_*128*DI_],  g_xpw_l[L_*128*DI_];  // N padded 96->128
__device__ __align__(16) __nv_bfloat16 g_dtw_h[L_*DI_*DR_],  g_dtw_l[L_*DI_*DR_];

// ---------------- helpers ----------------
__device__ __forceinline__ float siluf(float x) { return x / (1.f + __expf(-x)); }
__device__ __forceinline__ float softplusf(float x) {
    return x > 20.f ? x : log1pf(__expf(x));
}
__device__ __forceinline__ void split_write(float x, __nv_bfloat16* h, __nv_bfloat16* l) {
    __nv_bfloat16 hv = __float2bfloat16(x);
    *h = hv;
    *l = __float2bfloat16(x - __bfloat162float(hv));
}
__device__ __forceinline__ uint32_t smem_u32(const void* p) {
    uint32_t a;
    asm("{ .reg .u64 t; cvta.to.shared.u64 t, %1; cvt.u32.u64 %0, t; }" : "=r"(a) : "l"(p));
    return a;
}

// ---------------- async copy / ldmatrix / mma primitives ----------------
__device__ __forceinline__ void cp16(uint32_t s, const void* g) {
    asm volatile("cp.async.ca.shared.global [%0], [%1], 16;" :: "r"(s), "l"(g));
}
__device__ __forceinline__ void cp_commit() {
    asm volatile("cp.async.commit_group;" ::: "memory");
}
template<int N>
__device__ __forceinline__ void cp_wait() {
    asm volatile("cp.async.wait_group %0;" :: "n"(N) : "memory");
}
#define LDSM4(r0,r1,r2,r3,addr) \
    asm volatile("ldmatrix.sync.aligned.m8n8.x4.shared.b16 {%0,%1,%2,%3}, [%4];" \
        : "=r"(r0),"=r"(r1),"=r"(r2),"=r"(r3) : "r"(addr))

__device__ __forceinline__ void mma16816(float* c, const uint32_t* a, const uint32_t* b) {
    asm volatile(
        "mma.sync.aligned.m16n8k16.row.col.f32.bf16.bf16.f32 "
        "{%0,%1,%2,%3}, {%4,%5,%6,%7}, {%8,%9}, {%0,%1,%2,%3};"
        : "+f"(c[0]), "+f"(c[1]), "+f"(c[2]), "+f"(c[3])
        : "r"(a[0]), "r"(a[1]), "r"(a[2]), "r"(a[3]), "r"(b[0]), "r"(b[1]));
}

// swizzled byte offset within a tile: row pitch 64B (32 bf16), 16B chunks,
// chunk ^= (row>>1)&3 -> conflict-free for both cp.async stores and ldmatrix reads
__device__ __forceinline__ uint32_t soff(int r, int ch) {
    return (uint32_t)(r * 64 + ((ch ^ ((r >> 1) & 3)) << 4));
}

// ---------------- pipelined bf16-split tensor-core GEMM ----------------
// C[M x NC] (+)= (Ah+Al)[M,K] * (Bh+Bl)[N,K]^T, 3-pass split (hh, hl, lh).
// BM=64, BN=128, BK=32, 128 threads (4 warps 2x2), warp tile 32x64.
// 3-stage cp.async pipeline, ldmatrix.x4 fragments.
// EPI: 0 = store, 1 = atomicAdd (masked n<NC), 2 = softplus(v+bias[n]) store.
#define STAGE_BYTES 24576   // AH 4K | AL 4K | BH 8K | BL 8K
#define GEMM_DYN    (3*STAGE_BYTES + 128)

template<int EPI>
__global__ void __launch_bounds__(128, 3)
tc_gemm(const __nv_bfloat16* __restrict__ Ah, const __nv_bfloat16* __restrict__ Al,
        const __nv_bfloat16* __restrict__ Bh, const __nv_bfloat16* __restrict__ Bl,
        const float* __restrict__ bias, float* __restrict__ C,
        int K, int NC, int ldc)
{
    extern __shared__ __align__(16) char dsm[];
    const uint32_t sb = (smem_u32(dsm) + 127u) & ~127u;

    const int tid  = threadIdx.x;
    const int lane = tid & 31;
    const int wid  = tid >> 5;
    const int wm   = wid >> 1;           // 0..1
    const int wn   = wid & 1;            // 0..1
    const int m0   = blockIdx.x * 64;
    const int n0   = blockIdx.y * 128;
    const int kPer = K / gridDim.z;
    const int kBeg = blockIdx.z * kPer;
    const int nIter = kPer >> 5;         // BK=32

    const __nv_bfloat16* gAh = Ah + (size_t)m0 * K + kBeg;
    const __nv_bfloat16* gAl = Al + (size_t)m0 * K + kBeg;
    const __nv_bfloat16* gBh = Bh + (size_t)n0 * K + kBeg;
    const __nv_bfloat16* gBl = Bl + (size_t)n0 * K + kBeg;

    // per-thread staging coordinates
    const int sr = tid >> 2;             // 0..31
    const int sc = tid & 3;              // 0..3

    // stage loader
    auto load_stage = [&](int slot, int kof) {
        const uint32_t st = sb + slot * STAGE_BYTES;
        #pragma unroll
        for (int p = 0; p < 2; p++) {
            int r = sr + p * 32;
            uint32_t so = st + soff(r, sc);
            size_t go = (size_t)r * K + kof + sc * 8;
            cp16(so,        gAh + go);
            cp16(so + 4096, gAl + go);
        }
        #pragma unroll
        for (int p = 0; p < 4; p++) {
            int r = sr + p * 32;
            uint32_t so = st + 8192 + soff(r, sc);
            size_t go = (size_t)r * K + kof + sc * 8;
            cp16(so,        gBh + go);
            cp16(so + 8192, gBl + go);
        }
    };

    float acc[2][8][4];
    #pragma unroll
    for (int mi = 0; mi < 2; mi++)
        #pragma unroll
        for (int ni = 0; ni < 8; ni++)
            #pragma unroll
            for (int q = 0; q < 4; q++) acc[mi][ni][q] = 0.f;

    // prologue: fill pipeline
    #pragma unroll
    for (int s = 0; s < 3; s++) {
        if (s < nIter) load_stage(s, s * 32);
        cp_commit();
    }

    const int g  = lane >> 3;            // 0..3 (ldmatrix sub-matrix group)
    const int lr = lane & 7;

    for (int it = 0; it < nIter; it++) {
        cp_wait<2>();
        __syncthreads();
        const uint32_t st = sb + (it % 3) * STAGE_BYTES;

        #pragma unroll
        for (int ks = 0; ks < 2; ks++) {
            const int kc8 = ks * 2;      // chunk base (kc/8)
            uint32_t aH[2][4], aL[2][4], bH[8][2], bL[8][2];
            // A fragments: rows wm*32 + mi*16, 16x16 per ldmatrix.x4
            #pragma unroll
            for (int mi = 0; mi < 2; mi++) {
                int r  = wm * 32 + mi * 16 + (g & 1) * 8 + lr;
                int ch = kc8 + (g >> 1);
                uint32_t ad = st + soff(r, ch);
                LDSM4(aH[mi][0], aH[mi][1], aH[mi][2], aH[mi][3], ad);
                LDSM4(aL[mi][0], aL[mi][1], aL[mi][2], aL[mi][3], ad + 4096);
            }
            // B fragments: rows wn*64 + t*16, n16 x k16 per ldmatrix.x4
            #pragma unroll
            for (int t = 0; t < 4; t++) {
                int r  = wn * 64 + t * 16 + (g >> 1) * 8 + lr;
                int ch = kc8 + (g & 1);
                uint32_t ad = st + 8192 + soff(r, ch);
                LDSM4(bH[2*t][0], bH[2*t][1], bH[2*t+1][0], bH[2*t+1][1], ad);
                LDSM4(bL[2*t][0], bL[2*t][1], bL[2*t+1][0], bL[2*t+1][1], ad + 8192);
            }
            // 3 passes: hh, hl, lh (16 independent accs per pass)
            #pragma unroll
            for (int mi = 0; mi < 2; mi++)
                #pragma unroll
                for (int ni = 0; ni < 8; ni++) mma16816(acc[mi][ni], aH[mi], bH[ni]);
            #pragma unroll
            for (int mi = 0; mi < 2; mi++)
                #pragma unroll
                for (int ni = 0; ni < 8; ni++) mma16816(acc[mi][ni], aH[mi], bL[ni]);
            #pragma unroll
            for (int mi = 0; mi < 2; mi++)
                #pragma unroll
                for (int ni = 0; ni < 8; ni++) mma16816(acc[mi][ni], aL[mi], bH[ni]);
        }
        __syncthreads();
        int ns = it + 3;
        if (ns < nIter) load_stage(ns % 3, ns * 32);
        cp_commit();
    }

    // epilogue
    #pragma unroll
    for (int mi = 0; mi < 2; mi++) {
        #pragma unroll
        for (int ni = 0; ni < 8; ni++) {
            int r  = m0 + wm * 32 + mi * 16 + (lane >> 2);
            int cc = n0 + wn * 64 + ni * 8 + (lane & 3) * 2;
            #pragma unroll
            for (int half = 0; half < 2; half++) {
                int rr = r + half * 8;
                float v0 = acc[mi][ni][half * 2];
                float v1 = acc[mi][ni][half * 2 + 1];
                if (EPI == 2) {
                    v0 = softplusf(v0 + bias[cc]);
                    v1 = softplusf(v1 + bias[cc + 1]);
                }
                size_t o = (size_t)rr * ldc + cc;
                if (EPI == 1) {
                    if (cc < NC)     atomicAdd(&C[o], v0);
                    if (cc + 1 < NC) atomicAdd(&C[o + 1], v1);
                } else {
                    *(float2*)(C + o) = make_float2(v0, v1);
                }
            }
        }
    }
}

// ---------------- fp32 split-K GEMM (prepend MLP only) ----------------
template<int BM, int BN, int BK, int TM, int TN>
__launch_bounds__((BM/TM)*(BN/TN), 2)
__global__ void gemm_f32(const float* __restrict__ Ap, int lda,
                         const float* __restrict__ Bp,
                         float* __restrict__ Cp,
                         int M, int N, int K) {
    constexpr int THREADS = (BM/TM)*(BN/TN);
    __shared__ float As[BK][BM];
    __shared__ float Bs[BK][BN];
    const int tid = threadIdx.x;
    const int tx  = tid % (BN/TN);
    const int ty  = tid / (BN/TN);
    const int m0  = blockIdx.x * BM;
    const int n0  = blockIdx.y * BN;
    int kl = K / gridDim.z;
    int kBeg = blockIdx.z * kl, kEnd = kBeg + kl;

    float acc[TM][TN];
    #pragma unroll
    for (int i = 0; i < TM; i++)
        #pragma unroll
        for (int j = 0; j < TN; j++) acc[i][j] = 0.f;

    for (int k0 = kBeg; k0 < kEnd; k0 += BK) {
        #pragma unroll
        for (int i = tid; i < BM*BK/4; i += THREADS) {
            int row = i / (BK/4);
            int kc  = (i % (BK/4)) * 4;
            float4 v = make_float4(0.f,0.f,0.f,0.f);
            if (m0 + row < M)
                v = *(const float4*)(Ap + (size_t)(m0+row)*lda + k0 + kc);
            As[kc+0][row] = v.x; As[kc+1][row] = v.y;
            As[kc+2][row] = v.z; As[kc+3][row] = v.w;
        }
        #pragma unroll
        for (int i = tid; i < BK*BN/4; i += THREADS) {
            int kr = i / (BN/4);
            int nc = (i % (BN/4)) * 4;
            float4 v = *(const float4*)(Bp + (size_t)(k0+kr)*N + n0 + nc);
            *(float4*)&Bs[kr][nc] = v;
        }
        __syncthreads();
        #pragma unroll
        for (int kk = 0; kk < BK; kk++) {
            float a[TM], b[TN];
            #pragma unroll
            for (int i = 0; i < TM; i += 4)
                *(float4*)&a[i] = *(const float4*)&As[kk][ty*TM + i];
            #pragma unroll
            for (int j = 0; j < TN; j += 4)
                *(float4*)&b[j] = *(const float4*)&Bs[kk][tx*TN + j];
            #pragma unroll
            for (int i = 0; i < TM; i++)
                #pragma unroll
                for (int j = 0; j < TN; j++)
                    acc[i][j] = fmaf(a[i], b[j], acc[i][j]);
        }
        __syncthreads();
    }
    #pragma unroll
    for (int i = 0; i < TM; i++) {
        int m = m0 + ty*TM + i;
        if (m >= M) continue;
        #pragma unroll
        for (int j = 0; j < TN; j++) {
            int n = n0 + tx*TN + j;
            atomicAdd(&Cp[(size_t)m*N + n], acc[i][j]);
        }
    }
}

// ---------------- split / prep kernels ----------------
__global__ void split2_kernel(const float* __restrict__ in,
                              __nv_bfloat16* __restrict__ h,
                              __nv_bfloat16* __restrict__ l, int n) {
    int i = blockIdx.x * 256 + threadIdx.x;
    if (i >= n) return;
    split_write(in[i], h + i, l + i);
}

__global__ void split_xpw_kernel(const float* __restrict__ in,
                                 __nv_bfloat16* __restrict__ h,
                                 __nv_bfloat16* __restrict__ l) {
    int i = blockIdx.x * 256 + threadIdx.x;
    if (i >= L_ * 128 * DI_) return;
    int k    = i % DI_;
    int nrow = (i / DI_) % 128;
    int lay  = i / (128 * DI_);
    float x = (nrow < 96) ? in[(size_t)lay * 96 * DI_ + (size_t)nrow * DI_ + k] : 0.f;
    split_write(x, h + i, l + i);
}

__global__ void split_dtr_kernel(const float* __restrict__ xdbl,
                                 __nv_bfloat16* __restrict__ h,
                                 __nv_bfloat16* __restrict__ l) {
    int i = blockIdx.x * 256 + threadIdx.x;
    if (i >= M_ * DR_) return;
    int m = i / DR_, c = i % DR_;
    split_write(xdbl[(size_t)m * 96 + c], h + i, l + i);
}

__global__ void zero_kernel(float* __restrict__ p, int n) {
    int i = blockIdx.x * blockDim.x + threadIdx.x;
    if (i < n) p[i] = 0.f;
}

__global__ void silu_kernel(float* __restrict__ p, int n) {
    int i = blockIdx.x * blockDim.x + threadIdx.x;
    if (i < n) p[i] = siluf(p[i]);
}

__global__ void build_h_kernel(const float* __restrict__ p,
                               const float* __restrict__ x,
                               float* __restrict__ h) {
    int idx = blockIdx.x * blockDim.x + threadIdx.x;
    if (idx >= M_*D_) return;
    int d = idx % D_;
    int m = idx / D_;
    int b = m / T_;
    int t = m % T_;
    h[idx] = (t < P_) ? p[(size_t)(b*P_ + t)*D_ + d]
                      : x[(size_t)(b*S_ + (t - P_))*D_ + d];
}

__global__ void rmsnorm_split_kernel(const float* __restrict__ in,
                                     const float* __restrict__ w,
                                     __nv_bfloat16* __restrict__ oh,
                                     __nv_bfloat16* __restrict__ ol) {
    int row = blockIdx.x;
    int tid = threadIdx.x;
    const float4* r = (const float4*)(in + (size_t)row*D_);
    float4 x4 = r[tid];
    float s = x4.x*x4.x + x4.y*x4.y + x4.z*x4.z + x4.w*x4.w;
    #pragma unroll
    for (int o = 16; o; o >>= 1) s += __shfl_xor_sync(0xffffffffu, s, o);
    __shared__ float ws[8];
    __shared__ float scale_s;
    if ((tid & 31) == 0) ws[tid >> 5] = s;
    __syncthreads();
    if (tid == 0) {
        float t = 0.f;
        #pragma unroll
        for (int i = 0; i < 8; i++) t += ws[i];
        scale_s = rsqrtf(t / (float)D_ + 1e-5f);
    }
    __syncthreads();
    float sc = scale_s;
    float4 wv = ((const float4*)w)[tid];
    float v[4] = { x4.x*sc*wv.x, x4.y*sc*wv.y, x4.z*sc*wv.z, x4.w*sc*wv.w };
    size_t base = (size_t)row*D_ + tid*4;
    #pragma unroll
    for (int q = 0; q < 4; q++)
        split_write(v[q], oh + base + q, ol + base + q);
}

__global__ void final_kernel(const float* __restrict__ hin,
                             const float* __restrict__ w,
                             float* __restrict__ out) {
    int row = blockIdx.x;
    int b = row >> 9;
    int t = row & 511;
    int hrow = b*T_ + P_ + t;
    int tid = threadIdx.x;
    const float4* r = (const float4*)(hin + (size_t)hrow*D_);
    float4 x4 = r[tid];
    float s = x4.x*x4.x + x4.y*x4.y + x4.z*x4.z + x4.w*x4.w;
    #pragma unroll
    for (int o = 16; o; o >>= 1) s += __shfl_xor_sync(0xffffffffu, s, o);
    __shared__ float ws[8];
    __shared__ float scale_s;
    if ((tid & 31) == 0) ws[tid >> 5] = s;
    __syncthreads();
    if (tid == 0) {
        float tt = 0.f;
        #pragma unroll
        for (int i = 0; i < 8; i++) tt += ws[i];
        scale_s = rsqrtf(tt / (float)D_ + 1e-5f);
    }
    __syncthreads();
    float sc = scale_s;
    float4 wv = ((const float4*)w)[tid];
    float4 o4 = make_float4(x4.x*sc*wv.x, x4.y*sc*wv.y, x4.z*sc*wv.z, x4.w*sc*wv.w);
    ((float4*)(out + (size_t)row*D_))[tid] = o4;
}

__global__ void conv_silu_kernel(const float* __restrict__ xz,
                                 const float* __restrict__ cw,
                                 const float* __restrict__ cb,
                                 float* __restrict__ xi,
                                 __nv_bfloat16* __restrict__ xih,
                                 __nv_bfloat16* __restrict__ xil) {
    int idx = blockIdx.x * blockDim.x + threadIdx.x;
    if (idx >= M_*DI_) return;
    int e = idx % DI_;
    int m = idx / DI_;
    int t = m % T_;
    float4 w4 = ((const float4*)cw)[e];
    float wj[4] = {w4.x, w4.y, w4.z, w4.w};
    float acc = cb[e];
    #pragma unroll
    for (int j = 0; j < 4; j++) {
        int tt = t - 3 + j;
        if (tt >= 0)
            acc = fmaf(xz[(size_t)(m - 3 + j)*(2*DI_) + e], wj[j], acc);
    }
    float v = siluf(acc);
    size_t o = (size_t)m*DI_ + e;
    xi[o] = v;
    split_write(v, xih + o, xil + o);
}

// selective scan: warp = 2 channels x 16 states; 8-timestep batches for SHFL ILP.
__global__ void scan_kernel(const float* __restrict__ xz,
                            const float* __restrict__ xi,
                            const float* __restrict__ xdbl,
                            const float* __restrict__ dt,
                            const float* __restrict__ A_log,
                            const float* __restrict__ Dp,
                            __nv_bfloat16* __restrict__ yh,
                            __nv_bfloat16* __restrict__ yl) {
    int lane = threadIdx.x & 31;
    int warp = threadIdx.x >> 5;
    int pair = blockIdx.x * 4 + warp;
    int b = pair >> 10;
    int e = ((pair & 1023) << 1) + (lane >> 4);
    int s = lane & 15;

    float A  = -expf(A_log[(size_t)e*DS_ + s]);
    float Dv = Dp[e];
    float h  = 0.f;
    int m0 = b * T_;

    const float* dt_p = dt   + (size_t)m0*DI_ + e;
    const float* xi_p = xi   + (size_t)m0*DI_ + e;
    const float* z_p  = xz   + (size_t)m0*(2*DI_) + DI_ + e;
    const float* bc_p = xdbl + (size_t)m0*96 + DR_ + s;
    size_t ybase = (size_t)m0*DI_ + e;

    for (int tb = 0; tb < T_; tb += 8) {
        float dtv[8], xiv[8], Bv[8], Cv[8], zv[8];
        #pragma unroll
        for (int j = 0; j < 8; j++) {
            size_t t = tb + j;
            dtv[j] = dt_p[t*DI_];
            xiv[j] = xi_p[t*DI_];
            zv[j]  = z_p [t*(2*DI_)];
            Bv[j]  = bc_p[t*96];
            Cv[j]  = bc_p[t*96 + 16];
        }
        float p[8];
        #pragma unroll
        for (int j = 0; j < 8; j++) {
            float dA = __expf(dtv[j] * A);
            h = fmaf(dA, h, dtv[j] * Bv[j] * xiv[j]);
            p[j] = h * Cv[j];
        }
        #pragma unroll
        for (int o = 8; o >= 1; o >>= 1)
            #pragma unroll
            for (int j = 0; j < 8; j++)
                p[j] += __shfl_xor_sync(0xffffffffu, p[j], o);
        if (s == 0) {
            #pragma unroll
            for (int j = 0; j < 8; j++) {
                float val = (p[j] + xiv[j] * Dv) * siluf(zv[j]);
                size_t o2 = ybase + (size_t)(tb + j) * DI_;
                __nv_bfloat16 hv = __float2bfloat16(val);
                yh[o2] = hv;
                yl[o2] = __float2bfloat16(val - __bfloat162float(hv));
            }
        }
    }
}

// ---------------- host orchestration ----------------
extern "C" void kernel_launch(void* const* d_in, const int* in_sizes, int n_in,
                              void* d_out, int out_size) {
    (void)in_sizes; (void)n_in; (void)out_size;
    const float* x      = (const float*)d_in[0];
    const float* pc     = (const float*)d_in[1];
    const float* w1     = (const float*)d_in[2];
    const float* w2     = (const float*)d_in[3];
    const float* norm_w = (const float*)d_in[4];
    const float* ipw    = (const float*)d_in[5];
    const float* cw     = (const float*)d_in[6];
    const float* cb     = (const float*)d_in[7];
    const float* xpw    = (const float*)d_in[8];
    const float* dtw    = (const float*)d_in[9];
    const float* dtb    = (const float*)d_in[10];
    const float* A_log  = (const float*)d_in[11];
    const float* Dparam = (const float*)d_in[12];
    const float* opw    = (const float*)d_in[13];
    const float* fnw    = (const float*)d_in[14];

    float *h, *xzp, *xip, *dtp, *xdblp, *p1, *p2;
    cudaGetSymbolAddress((void**)&h,     g_h);
    cudaGetSymbolAddress((void**)&xzp,   g_xz);
    cudaGetSymbolAddress((void**)&xip,   g_xi);
    cudaGetSymbolAddress((void**)&dtp,   g_dt);
    cudaGetSymbolAddress((void**)&xdblp, g_xdbl);
    cudaGetSymbolAddress((void**)&p1,    g_p1);
    cudaGetSymbolAddress((void**)&p2,    g_p2);

    __nv_bfloat16 *xnh, *xnl, *xih, *xil, *yh, *yl, *dtrh, *dtrl;
    __nv_bfloat16 *ipwh, *ipwl, *opwh, *opwl, *xpwh, *xpwl, *dtwh, *dtwl;
    cudaGetSymbolAddress((void**)&xnh,  g_xn_h);  cudaGetSymbolAddress((void**)&xnl,  g_xn_l);
    cudaGetSymbolAddress((void**)&xih,  g_xi_h);  cudaGetSymbolAddress((void**)&xil,  g_xi_l);
    cudaGetSymbolAddress((void**)&yh,   g_y_h);   cudaGetSymbolAddress((void**)&yl,   g_y_l);
    cudaGetSymbolAddress((void**)&dtrh, g_dtr_h); cudaGetSymbolAddress((void**)&dtrl, g_dtr_l);
    cudaGetSymbolAddress((void**)&ipwh, g_ipw_h); cudaGetSymbolAddress((void**)&ipwl, g_ipw_l);
    cudaGetSymbolAddress((void**)&opwh, g_opw_h); cudaGetSymbolAddress((void**)&opwl, g_opw_l);
    cudaGetSymbolAddress((void**)&xpwh, g_xpw_h); cudaGetSymbolAddress((void**)&xpwl, g_xpw_l);
    cudaGetSymbolAddress((void**)&dtwh, g_dtw_h); cudaGetSymbolAddress((void**)&dtwl, g_dtw_l);

    cudaFuncSetAttribute(tc_gemm<0>, cudaFuncAttributeMaxDynamicSharedMemorySize, GEMM_DYN);
    cudaFuncSetAttribute(tc_gemm<1>, cudaFuncAttributeMaxDynamicSharedMemorySize, GEMM_DYN);
    cudaFuncSetAttribute(tc_gemm<2>, cudaFuncAttributeMaxDynamicSharedMemorySize, GEMM_DYN);

    // ---- weight splits ----
    {
        int n;
        n = L_*2*DI_*D_;  split2_kernel<<<(n+255)/256, 256>>>(ipw, ipwh, ipwl, n);
        n = L_*D_*DI_;    split2_kernel<<<(n+255)/256, 256>>>(opw, opwh, opwl, n);
        n = L_*DI_*DR_;   split2_kernel<<<(n+255)/256, 256>>>(dtw, dtwh, dtwl, n);
        n = L_*128*DI_;   split_xpw_kernel<<<(n+255)/256, 256>>>(xpw, xpwh, xpwl);
    }

    // ---- prepend MLP: p = silu(pc @ w1) @ w2 (fp32) ----
    zero_kernel<<<(128*D_+255)/256, 256>>>(p1, 128*D_);
    gemm_f32<64,64,16,4,4><<<dim3(2,16,3), 256>>>(pc, PCD_, w1, p1, 128, D_, PCD_);
    silu_kernel<<<(128*D_+255)/256, 256>>>(p1, 128*D_);
    zero_kernel<<<(128*D_+255)/256, 256>>>(p2, 128*D_);
    gemm_f32<64,64,16,4,4><<<dim3(2,16,4), 256>>>(p1, D_, w2, p2, 128, D_, D_);
    build_h_kernel<<<(M_*D_+255)/256, 256>>>(p2, x, h);

    // ---- 4 mamba layers ----
    for (int l = 0; l < L_; l++) {
        rmsnorm_split_kernel<<<M_, 256>>>(h, norm_w + (size_t)l*D_, xnh, xnl);

        // xz = xn @ in_proj_w^T   [1152,1024] x [4096,1024]^T   (576 CTAs)
        tc_gemm<0><<<dim3(18, 32, 1), 128, GEMM_DYN>>>(
            xnh, xnl, ipwh + (size_t)l*2*DI_*D_, ipwl + (size_t)l*2*DI_*D_,
            nullptr, xzp, D_, 2*DI_, 2*DI_);

        conv_silu_kernel<<<(M_*DI_+255)/256, 256>>>(
            xzp, cw + (size_t)l*DI_*4, cb + (size_t)l*DI_, xip, xih, xil);

        // xdbl = xi @ x_proj_w^T  [1152,2048] x [96(pad128),2048]^T  split-K=16 (288 CTAs)
        zero_kernel<<<(M_*96+255)/256, 256>>>(xdblp, M_*96);
        tc_gemm<1><<<dim3(18, 1, 16), 128, GEMM_DYN>>>(
            xih, xil, xpwh + (size_t)l*128*DI_, xpwl + (size_t)l*128*DI_,
            nullptr, xdblp, DI_, 96, 96);

        split_dtr_kernel<<<(M_*DR_+255)/256, 256>>>(xdblp, dtrh, dtrl);

        // dt = softplus(dtr @ dt_proj_w^T + b)  [1152,64] x [2048,64]^T  (288 CTAs)
        tc_gemm<2><<<dim3(18, 16, 1), 128, GEMM_DYN>>>(
            dtrh, dtrl, dtwh + (size_t)l*DI_*DR_, dtwl + (size_t)l*DI_*DR_,
            dtb + (size_t)l*DI_, dtp, DR_, DI_, DI_);

        // selective scan + gate -> y splits
        scan_kernel<<<(B_*DI_/2)/4, 128>>>(
            xzp, xip, xdblp, dtp,
            A_log + (size_t)l*DI_*DS_, Dparam + (size_t)l*DI_, yh, yl);

        // h += y @ out_proj_w^T   [1152,2048] x [1024,2048]^T  split-K=4 (576 CTAs)
        tc_gemm<1><<<dim3(18, 8, 4), 128, GEMM_DYN>>>(
            yh, yl, opwh + (size_t)l*D_*DI_, opwl + (size_t)l*D_*DI_,
            nullptr, h, DI_, D_, D_);
    }

    // ---- final rmsnorm + slice ----
    final_kernel<<<B_*S_, 256>>>(h, fnw, (float*)d_out);
}

// round 5
// speedup vs baseline: 2.4824x; 1.2747x over previous
#include <cuda_runtime.h>
#include <cuda_bf16.h>
#include <math.h>
#include <stdint.h>

#define B_   2
#define S_   512
#define P_   64
#define T_   576
#define D_   1024
#define L_   4
#define DI_  2048
#define DS_  16
#define DR_  64
#define PCD_ 768
#define M_   (B_*T_)   // 1152

// ---------------- static scratch ----------------
__device__ float g_h   [M_*D_];
__device__ float g_xz  [M_*2*DI_];
__device__ float g_xi  [M_*DI_];
__device__ float g_dt  [M_*DI_];
__device__ float g_xdbl[M_*96];
__device__ float g_p1  [128*D_];
__device__ float g_p2  [128*D_];

__device__ __align__(16) __nv_bfloat16 g_xn_h [M_*D_],  g_xn_l [M_*D_];
__device__ __align__(16) __nv_bfloat16 g_xi_h [M_*DI_], g_xi_l [M_*DI_];
__device__ __align__(16) __nv_bfloat16 g_y_h  [M_*DI_], g_y_l  [M_*DI_];
__device__ __align__(16) __nv_bfloat16 g_dtr_h[M_*DR_], g_dtr_l[M_*DR_];

// weights: bf16 hi only (2-pass split keeps aH*bH + aL*bH)
__device__ __align__(16) __nv_bfloat16 g_ipw_h[L_*2*DI_*D_];
__device__ __align__(16) __nv_bfloat16 g_opw_h[L_*D_*DI_];
__device__ __align__(16) __nv_bfloat16 g_xpw_h[L_*128*DI_];   // N padded 96->128
__device__ __align__(16) __nv_bfloat16 g_dtw_h[L_*DI_*DR_];

// ---------------- helpers ----------------
__device__ __forceinline__ float siluf(float x) { return x / (1.f + __expf(-x)); }
__device__ __forceinline__ float softplusf(float x) {
    return x > 20.f ? x : log1pf(__expf(x));
}
__device__ __forceinline__ uint32_t smem_u32(const void* p) {
    uint32_t a;
    asm("{ .reg .u64 t; cvta.to.shared.u64 t, %1; cvt.u32.u64 %0, t; }" : "=r"(a) : "l"(p));
    return a;
}
__device__ __forceinline__ uint32_t pack2(float a, float b) {
    __nv_bfloat162 t = __floats2bfloat162_rn(a, b);
    return *(uint32_t*)&t;
}
// split 4 floats into hi/lo bf16 quads, store as 8B each
__device__ __forceinline__ void split_store4(float4 v,
                                             __nv_bfloat16* __restrict__ hp,
                                             __nv_bfloat16* __restrict__ lp,
                                             size_t i4) {
    float hx = __bfloat162float(__float2bfloat16(v.x));
    float hy = __bfloat162float(__float2bfloat16(v.y));
    float hz = __bfloat162float(__float2bfloat16(v.z));
    float hw = __bfloat162float(__float2bfloat16(v.w));
    uint2 ho, lo;
    ho.x = pack2(hx, hy);             ho.y = pack2(hz, hw);
    lo.x = pack2(v.x - hx, v.y - hy); lo.y = pack2(v.z - hz, v.w - hw);
    ((uint2*)hp)[i4] = ho;
    ((uint2*)lp)[i4] = lo;
}

// ---------------- async copy / ldmatrix / mma primitives ----------------
__device__ __forceinline__ void cp16(uint32_t s, const void* g) {
    asm volatile("cp.async.ca.shared.global [%0], [%1], 16;" :: "r"(s), "l"(g));
}
__device__ __forceinline__ void cp_commit() {
    asm volatile("cp.async.commit_group;" ::: "memory");
}
template<int N>
__device__ __forceinline__ void cp_wait() {
    asm volatile("cp.async.wait_group %0;" :: "n"(N) : "memory");
}
#define LDSM4(r0,r1,r2,r3,addr) \
    asm volatile("ldmatrix.sync.aligned.m8n8.x4.shared.b16 {%0,%1,%2,%3}, [%4];" \
        : "=r"(r0),"=r"(r1),"=r"(r2),"=r"(r3) : "r"(addr))

__device__ __forceinline__ void mma16816(float* c, const uint32_t* a, const uint32_t* b) {
    asm volatile(
        "mma.sync.aligned.m16n8k16.row.col.f32.bf16.bf16.f32 "
        "{%0,%1,%2,%3}, {%4,%5,%6,%7}, {%8,%9}, {%0,%1,%2,%3};"
        : "+f"(c[0]), "+f"(c[1]), "+f"(c[2]), "+f"(c[3])
        : "r"(a[0]), "r"(a[1]), "r"(a[2]), "r"(a[3]), "r"(b[0]), "r"(b[1]));
}

// swizzled byte offset within a tile: row pitch 64B (32 bf16), 16B chunks
__device__ __forceinline__ uint32_t soff(int r, int ch) {
    return (uint32_t)(r * 64 + ((ch ^ ((r >> 1) & 3)) << 4));
}

// ---------------- pipelined bf16-split tensor-core GEMM (2-pass) ----------------
// C[M x NC] (+)= (Ah+Al)[M,K] * Bh[N,K]^T   (weights bf16 hi only)
// BM=64, BN=128, BK=32, 128 threads (4 warps 2x2), warp tile 32x64.
// 4-stage cp.async pipeline, single __syncthreads per iteration.
// EPI: 0 = store, 1 = atomicAdd (masked n<NC), 2 = softplus(v+bias[n]) store.
#define STAGE_BYTES 16384   // AH 4K | AL 4K | BH 8K
#define NSTAGE 4
#define GEMM_DYN (NSTAGE*STAGE_BYTES + 128)

template<int EPI>
__global__ void __launch_bounds__(128, 3)
tc_gemm(const __nv_bfloat16* __restrict__ Ah, const __nv_bfloat16* __restrict__ Al,
        const __nv_bfloat16* __restrict__ Bh,
        const float* __restrict__ bias, float* __restrict__ C,
        int K, int NC, int ldc)
{
    extern __shared__ __align__(16) char dsm[];
    const uint32_t sb = (smem_u32(dsm) + 127u) & ~127u;

    const int tid  = threadIdx.x;
    const int lane = tid & 31;
    const int wid  = tid >> 5;
    const int wm   = wid >> 1;           // 0..1
    const int wn   = wid & 1;            // 0..1
    const int m0   = blockIdx.x * 64;
    const int n0   = blockIdx.y * 128;
    const int kPer = K / gridDim.z;
    const int kBeg = blockIdx.z * kPer;
    const int nIter = kPer >> 5;         // BK=32

    const __nv_bfloat16* gAh = Ah + (size_t)m0 * K + kBeg;
    const __nv_bfloat16* gAl = Al + (size_t)m0 * K + kBeg;
    const __nv_bfloat16* gBh = Bh + (size_t)n0 * K + kBeg;

    const int sr = tid >> 2;             // 0..31
    const int sc = tid & 3;              // 0..3

    auto load_stage = [&](int slot, int kof) {
        const uint32_t st = sb + slot * STAGE_BYTES;
        #pragma unroll
        for (int p = 0; p < 2; p++) {
            int r = sr + p * 32;
            uint32_t so = st + soff(r, sc);
            size_t go = (size_t)r * K + kof + sc * 8;
            cp16(so,        gAh + go);
            cp16(so + 4096, gAl + go);
        }
        #pragma unroll
        for (int p = 0; p < 4; p++) {
            int r = sr + p * 32;
            cp16(st + 8192 + soff(r, sc), gBh + (size_t)r * K + kof + sc * 8);
        }
    };

    float acc[2][8][4];
    #pragma unroll
    for (int mi = 0; mi < 2; mi++)
        #pragma unroll
        for (int ni = 0; ni < 8; ni++)
            #pragma unroll
            for (int q = 0; q < 4; q++) acc[mi][ni][q] = 0.f;

    // prologue: NSTAGE-1 stages
    #pragma unroll
    for (int s = 0; s < NSTAGE - 1; s++) {
        if (s < nIter) load_stage(s, s * 32);
        cp_commit();
    }

    const int g  = lane >> 3;
    const int lr = lane & 7;

    for (int it = 0; it < nIter; it++) {
        cp_wait<NSTAGE - 2>();
        __syncthreads();
        // issue next load BEFORE compute; its slot == slot computed at it-1,
        // which all warps finished before this barrier.
        int ns = it + NSTAGE - 1;
        if (ns < nIter) load_stage(ns & 3, ns * 32);
        cp_commit();

        const uint32_t st = sb + (it & 3) * STAGE_BYTES;
        #pragma unroll
        for (int ks = 0; ks < 2; ks++) {
            const int kc8 = ks * 2;
            uint32_t aH[2][4], aL[2][4], bH[8][2];
            #pragma unroll
            for (int mi = 0; mi < 2; mi++) {
                int r  = wm * 32 + mi * 16 + (g & 1) * 8 + lr;
                int ch = kc8 + (g >> 1);
                uint32_t ad = st + soff(r, ch);
                LDSM4(aH[mi][0], aH[mi][1], aH[mi][2], aH[mi][3], ad);
                LDSM4(aL[mi][0], aL[mi][1], aL[mi][2], aL[mi][3], ad + 4096);
            }
            #pragma unroll
            for (int t = 0; t < 4; t++) {
                int r  = wn * 64 + t * 16 + (g >> 1) * 8 + lr;
                int ch = kc8 + (g & 1);
                uint32_t ad = st + 8192 + soff(r, ch);
                LDSM4(bH[2*t][0], bH[2*t][1], bH[2*t+1][0], bH[2*t+1][1], ad);
            }
            #pragma unroll
            for (int mi = 0; mi < 2; mi++)
                #pragma unroll
                for (int ni = 0; ni < 8; ni++) mma16816(acc[mi][ni], aH[mi], bH[ni]);
            #pragma unroll
            for (int mi = 0; mi < 2; mi++)
                #pragma unroll
                for (int ni = 0; ni < 8; ni++) mma16816(acc[mi][ni], aL[mi], bH[ni]);
        }
    }

    // epilogue
    #pragma unroll
    for (int mi = 0; mi < 2; mi++) {
        #pragma unroll
        for (int ni = 0; ni < 8; ni++) {
            int r  = m0 + wm * 32 + mi * 16 + (lane >> 2);
            int cc = n0 + wn * 64 + ni * 8 + (lane & 3) * 2;
            #pragma unroll
            for (int half = 0; half < 2; half++) {
                int rr = r + half * 8;
                float v0 = acc[mi][ni][half * 2];
                float v1 = acc[mi][ni][half * 2 + 1];
                if (EPI == 2) {
                    v0 = softplusf(v0 + bias[cc]);
                    v1 = softplusf(v1 + bias[cc + 1]);
                }
                size_t o = (size_t)rr * ldc + cc;
                if (EPI == 1) {
                    if (cc < NC)     atomicAdd(&C[o], v0);
                    if (cc + 1 < NC) atomicAdd(&C[o + 1], v1);
                } else {
                    *(float2*)(C + o) = make_float2(v0, v1);
                }
            }
        }
    }
}

// ---------------- fp32 split-K GEMM (prepend MLP only) ----------------
template<int BM, int BN, int BK, int TM, int TN>
__launch_bounds__((BM/TM)*(BN/TN), 2)
__global__ void gemm_f32(const float* __restrict__ Ap, int lda,
                         const float* __restrict__ Bp,
                         float* __restrict__ Cp,
                         int M, int N, int K) {
    constexpr int THREADS = (BM/TM)*(BN/TN);
    __shared__ float As[BK][BM];
    __shared__ float Bs[BK][BN];
    const int tid = threadIdx.x;
    const int tx  = tid % (BN/TN);
    const int ty  = tid / (BN/TN);
    const int m0  = blockIdx.x * BM;
    const int n0  = blockIdx.y * BN;
    int kl = K / gridDim.z;
    int kBeg = blockIdx.z * kl, kEnd = kBeg + kl;

    float acc[TM][TN];
    #pragma unroll
    for (int i = 0; i < TM; i++)
        #pragma unroll
        for (int j = 0; j < TN; j++) acc[i][j] = 0.f;

    for (int k0 = kBeg; k0 < kEnd; k0 += BK) {
        #pragma unroll
        for (int i = tid; i < BM*BK/4; i += THREADS) {
            int row = i / (BK/4);
            int kc  = (i % (BK/4)) * 4;
            float4 v = make_float4(0.f,0.f,0.f,0.f);
            if (m0 + row < M)
                v = *(const float4*)(Ap + (size_t)(m0+row)*lda + k0 + kc);
            As[kc+0][row] = v.x; As[kc+1][row] = v.y;
            As[kc+2][row] = v.z; As[kc+3][row] = v.w;
        }
        #pragma unroll
        for (int i = tid; i < BK*BN/4; i += THREADS) {
            int kr = i / (BN/4);
            int nc = (i % (BN/4)) * 4;
            float4 v = *(const float4*)(Bp + (size_t)(k0+kr)*N + n0 + nc);
            *(float4*)&Bs[kr][nc] = v;
        }
        __syncthreads();
        #pragma unroll
        for (int kk = 0; kk < BK; kk++) {
            float a[TM], b[TN];
            #pragma unroll
            for (int i = 0; i < TM; i += 4)
                *(float4*)&a[i] = *(const float4*)&As[kk][ty*TM + i];
            #pragma unroll
            for (int j = 0; j < TN; j += 4)
                *(float4*)&b[j] = *(const float4*)&Bs[kk][tx*TN + j];
            #pragma unroll
            for (int i = 0; i < TM; i++)
                #pragma unroll
                for (int j = 0; j < TN; j++)
                    acc[i][j] = fmaf(a[i], b[j], acc[i][j]);
        }
        __syncthreads();
    }
    #pragma unroll
    for (int i = 0; i < TM; i++) {
        int m = m0 + ty*TM + i;
        if (m >= M) continue;
        #pragma unroll
        for (int j = 0; j < TN; j++) {
            int n = n0 + tx*TN + j;
            atomicAdd(&Cp[(size_t)m*N + n], acc[i][j]);
        }
    }
}

// ---------------- convert / split kernels (vectorized x4) ----------------
__global__ void convert_w4(const float* __restrict__ in,
                           __nv_bfloat16* __restrict__ h, int n4) {
    int i = blockIdx.x * 256 + threadIdx.x;
    if (i >= n4) return;
    float4 v = ((const float4*)in)[i];
    uint2 o;
    o.x = pack2(v.x, v.y);
    o.y = pack2(v.z, v.w);
    ((uint2*)h)[i] = o;
}

// x_proj weights: [L][96][DI] -> padded [L][128][DI], hi only
__global__ void convert_xpw4(const float* __restrict__ in,
                             __nv_bfloat16* __restrict__ h) {
    int i = blockIdx.x * 256 + threadIdx.x;
    if (i >= L_ * 128 * (DI_/4)) return;
    int k4   = i % (DI_/4);
    int nrow = (i / (DI_/4)) % 128;
    int lay  = i / (128 * (DI_/4));
    float4 v = make_float4(0.f, 0.f, 0.f, 0.f);
    if (nrow < 96)
        v = ((const float4*)in)[(size_t)(lay * 96 + nrow) * (DI_/4) + k4];
    uint2 o;
    o.x = pack2(v.x, v.y);
    o.y = pack2(v.z, v.w);
    ((uint2*)h)[i] = o;
}

// dt_rank columns of xdbl -> contiguous [M][64] hi/lo split
__global__ void split_dtr4(const float* __restrict__ xdbl,
                           __nv_bfloat16* __restrict__ h,
                           __nv_bfloat16* __restrict__ l) {
    int i = blockIdx.x * 256 + threadIdx.x;
    if (i >= M_ * (DR_/4)) return;
    int m = i / (DR_/4), c4 = i % (DR_/4);
    float4 v = ((const float4*)xdbl)[(size_t)m * 24 + c4];
    split_store4(v, h, l, i);
}

__global__ void zero_kernel(float* __restrict__ p, int n) {
    int i = blockIdx.x * blockDim.x + threadIdx.x;
    if (i < n) p[i] = 0.f;
}

__global__ void silu_kernel(float* __restrict__ p, int n) {
    int i = blockIdx.x * blockDim.x + threadIdx.x;
    if (i < n) p[i] = siluf(p[i]);
}

__global__ void build_h_kernel(const float* __restrict__ p,
                               const float* __restrict__ x,
                               float* __restrict__ h) {
    int idx = blockIdx.x * blockDim.x + threadIdx.x;
    if (idx >= M_*D_) return;
    int d = idx % D_;
    int m = idx / D_;
    int b = m / T_;
    int t = m % T_;
    h[idx] = (t < P_) ? p[(size_t)(b*P_ + t)*D_ + d]
                      : x[(size_t)(b*S_ + (t - P_))*D_ + d];
}

__global__ void rmsnorm_split_kernel(const float* __restrict__ in,
                                     const float* __restrict__ w,
                                     __nv_bfloat16* __restrict__ oh,
                                     __nv_bfloat16* __restrict__ ol) {
    int row = blockIdx.x;
    int tid = threadIdx.x;
    const float4* r = (const float4*)(in + (size_t)row*D_);
    float4 x4 = r[tid];
    float s = x4.x*x4.x + x4.y*x4.y + x4.z*x4.z + x4.w*x4.w;
    #pragma unroll
    for (int o = 16; o; o >>= 1) s += __shfl_xor_sync(0xffffffffu, s, o);
    __shared__ float ws[8];
    __shared__ float scale_s;
    if ((tid & 31) == 0) ws[tid >> 5] = s;
    __syncthreads();
    if (tid == 0) {
        float t = 0.f;
        #pragma unroll
        for (int i = 0; i < 8; i++) t += ws[i];
        scale_s = rsqrtf(t / (float)D_ + 1e-5f);
    }
    __syncthreads();
    float sc = scale_s;
    float4 wv = ((const float4*)w)[tid];
    float4 v = make_float4(x4.x*sc*wv.x, x4.y*sc*wv.y, x4.z*sc*wv.z, x4.w*sc*wv.w);
    split_store4(v, oh, ol, (size_t)row*(D_/4) + tid);
}

__global__ void final_kernel(const float* __restrict__ hin,
                             const float* __restrict__ w,
                             float* __restrict__ out) {
    int row = blockIdx.x;
    int b = row >> 9;
    int t = row & 511;
    int hrow = b*T_ + P_ + t;
    int tid = threadIdx.x;
    const float4* r = (const float4*)(hin + (size_t)hrow*D_);
    float4 x4 = r[tid];
    float s = x4.x*x4.x + x4.y*x4.y + x4.z*x4.z + x4.w*x4.w;
    #pragma unroll
    for (int o = 16; o; o >>= 1) s += __shfl_xor_sync(0xffffffffu, s, o);
    __shared__ float ws[8];
    __shared__ float scale_s;
    if ((tid & 31) == 0) ws[tid >> 5] = s;
    __syncthreads();
    if (tid == 0) {
        float tt = 0.f;
        #pragma unroll
        for (int i = 0; i < 8; i++) tt += ws[i];
        scale_s = rsqrtf(tt / (float)D_ + 1e-5f);
    }
    __syncthreads();
    float sc = scale_s;
    float4 wv = ((const float4*)w)[tid];
    float4 o4 = make_float4(x4.x*sc*wv.x, x4.y*sc*wv.y, x4.z*sc*wv.z, x4.w*sc*wv.w);
    ((float4*)(out + (size_t)row*D_))[tid] = o4;
}

// depthwise causal conv (DC=4) + silu, 4 channels/thread; also zeroes xdbl
__global__ void conv_silu4(const float* __restrict__ xz,
                           const float* __restrict__ cw,
                           const float* __restrict__ cb,
                           float* __restrict__ xi,
                           __nv_bfloat16* __restrict__ xih,
                           __nv_bfloat16* __restrict__ xil,
                           float* __restrict__ xdbl) {
    int idx = blockIdx.x * blockDim.x + threadIdx.x;
    if (idx >= M_*(DI_/4)) return;
    if (idx < M_*96/4) ((float4*)xdbl)[idx] = make_float4(0.f,0.f,0.f,0.f);

    int e4 = idx % (DI_/4);
    int m  = idx / (DI_/4);
    int t  = m % T_;
    float4 w0 = ((const float4*)cw)[e4*4+0];
    float4 w1 = ((const float4*)cw)[e4*4+1];
    float4 w2 = ((const float4*)cw)[e4*4+2];
    float4 w3 = ((const float4*)cw)[e4*4+3];
    float4 acc = ((const float4*)cb)[e4];
    const float* wj[4] = { (const float*)&w0, (const float*)&w1,
                           (const float*)&w2, (const float*)&w3 };
    #pragma unroll
    for (int j = 0; j < 4; j++) {
        int tt = t - 3 + j;
        if (tt >= 0) {
            float4 xv = ((const float4*)(xz + (size_t)(m - 3 + j)*(2*DI_)))[e4];
            acc.x = fmaf(xv.x, wj[0][j], acc.x);
            acc.y = fmaf(xv.y, wj[1][j], acc.y);
            acc.z = fmaf(xv.z, wj[2][j], acc.z);
            acc.w = fmaf(xv.w, wj[3][j], acc.w);
        }
    }
    float4 v = make_float4(siluf(acc.x), siluf(acc.y), siluf(acc.z), siluf(acc.w));
    ((float4*)xi)[idx] = v;
    split_store4(v, xih, xil, idx);
}

// selective scan: warp = 2 channels x 16 states; 8-timestep batches.
__global__ void scan_kernel(const float* __restrict__ xz,
                            const float* __restrict__ xi,
                            const float* __restrict__ xdbl,
                            const float* __restrict__ dt,
                            const float* __restrict__ A_log,
                            const float* __restrict__ Dp,
                            __nv_bfloat16* __restrict__ yh,
                            __nv_bfloat16* __restrict__ yl) {
    int lane = threadIdx.x & 31;
    int warp = threadIdx.x >> 5;
    int pair = blockIdx.x * 4 + warp;
    int b = pair >> 10;
    int e = ((pair & 1023) << 1) + (lane >> 4);
    int s = lane & 15;

    float A  = -expf(A_log[(size_t)e*DS_ + s]);
    float Dv = Dp[e];
    float h  = 0.f;
    int m0 = b * T_;

    const float* dt_p = dt   + (size_t)m0*DI_ + e;
    const float* xi_p = xi   + (size_t)m0*DI_ + e;
    const float* z_p  = xz   + (size_t)m0*(2*DI_) + DI_ + e;
    const float* bc_p = xdbl + (size_t)m0*96 + DR_ + s;
    size_t ybase = (size_t)m0*DI_ + (e & ~1);   // even channel of the pair

    for (int tb = 0; tb < T_; tb += 8) {
        float dtv[8], xiv[8], Bv[8], Cv[8], zv[8];
        #pragma unroll
        for (int j = 0; j < 8; j++) {
            size_t t = tb + j;
            dtv[j] = dt_p[t*DI_];
            xiv[j] = xi_p[t*DI_];
            zv[j]  = z_p [t*(2*DI_)];
            Bv[j]  = bc_p[t*96];
            Cv[j]  = bc_p[t*96 + 16];
        }
        float p[8];
        #pragma unroll
        for (int j = 0; j < 8; j++) {
            float dA = __expf(dtv[j] * A);
            h = fmaf(dA, h, dtv[j] * Bv[j] * xiv[j]);
            p[j] = h * Cv[j];
        }
        #pragma unroll
        for (int o = 8; o >= 1; o >>= 1)
            #pragma unroll
            for (int j = 0; j < 8; j++)
                p[j] += __shfl_xor_sync(0xffffffffu, p[j], o);
        #pragma unroll
        for (int j = 0; j < 8; j++) {
            float val = (p[j] + xiv[j] * Dv) * siluf(zv[j]);   // valid on all lanes
            float v1  = __shfl_down_sync(0xffffffffu, val, 16); // lane0 <- lane16 (e+1)
            if (lane == 0) {
                float h0 = __bfloat162float(__float2bfloat16(val));
                float h1 = __bfloat162float(__float2bfloat16(v1));
                size_t o2 = (ybase + (size_t)(tb + j) * DI_) >> 1;
                ((uint32_t*)yh)[o2] = pack2(h0, h1);
                ((uint32_t*)yl)[o2] = pack2(val - h0, v1 - h1);
            }
        }
    }
}

// ---------------- host orchestration ----------------
extern "C" void kernel_launch(void* const* d_in, const int* in_sizes, int n_in,
                              void* d_out, int out_size) {
    (void)in_sizes; (void)n_in; (void)out_size;
    const float* x      = (const float*)d_in[0];
    const float* pc     = (const float*)d_in[1];
    const float* w1     = (const float*)d_in[2];
    const float* w2     = (const float*)d_in[3];
    const float* norm_w = (const float*)d_in[4];
    const float* ipw    = (const float*)d_in[5];
    const float* cw     = (const float*)d_in[6];
    const float* cb     = (const float*)d_in[7];
    const float* xpw    = (const float*)d_in[8];
    const float* dtw    = (const float*)d_in[9];
    const float* dtb    = (const float*)d_in[10];
    const float* A_log  = (const float*)d_in[11];
    const float* Dparam = (const float*)d_in[12];
    const float* opw    = (const float*)d_in[13];
    const float* fnw    = (const float*)d_in[14];

    float *h, *xzp, *xip, *dtp, *xdblp, *p1, *p2;
    cudaGetSymbolAddress((void**)&h,     g_h);
    cudaGetSymbolAddress((void**)&xzp,   g_xz);
    cudaGetSymbolAddress((void**)&xip,   g_xi);
    cudaGetSymbolAddress((void**)&dtp,   g_dt);
    cudaGetSymbolAddress((void**)&xdblp, g_xdbl);
    cudaGetSymbolAddress((void**)&p1,    g_p1);
    cudaGetSymbolAddress((void**)&p2,    g_p2);

    __nv_bfloat16 *xnh, *xnl, *xih, *xil, *yh, *yl, *dtrh, *dtrl;
    __nv_bfloat16 *ipwh, *opwh, *xpwh, *dtwh;
    cudaGetSymbolAddress((void**)&xnh,  g_xn_h);  cudaGetSymbolAddress((void**)&xnl,  g_xn_l);
    cudaGetSymbolAddress((void**)&xih,  g_xi_h);  cudaGetSymbolAddress((void**)&xil,  g_xi_l);
    cudaGetSymbolAddress((void**)&yh,   g_y_h);   cudaGetSymbolAddress((void**)&yl,   g_y_l);
    cudaGetSymbolAddress((void**)&dtrh, g_dtr_h); cudaGetSymbolAddress((void**)&dtrl, g_dtr_l);
    cudaGetSymbolAddress((void**)&ipwh, g_ipw_h);
    cudaGetSymbolAddress((void**)&opwh, g_opw_h);
    cudaGetSymbolAddress((void**)&xpwh, g_xpw_h);
    cudaGetSymbolAddress((void**)&dtwh, g_dtw_h);

    cudaFuncSetAttribute(tc_gemm<0>, cudaFuncAttributeMaxDynamicSharedMemorySize, GEMM_DYN);
    cudaFuncSetAttribute(tc_gemm<1>, cudaFuncAttributeMaxDynamicSharedMemorySize, GEMM_DYN);
    cudaFuncSetAttribute(tc_gemm<2>, cudaFuncAttributeMaxDynamicSharedMemorySize, GEMM_DYN);

    // ---- weight converts (fp32 -> bf16 hi, vectorized) ----
    {
        int n4;
        n4 = L_*2*DI_*D_/4; convert_w4<<<(n4+255)/256, 256>>>(ipw, ipwh, n4);
        n4 = L_*D_*DI_/4;   convert_w4<<<(n4+255)/256, 256>>>(opw, opwh, n4);
        n4 = L_*DI_*DR_/4;  convert_w4<<<(n4+255)/256, 256>>>(dtw, dtwh, n4);
        n4 = L_*128*DI_/4;  convert_xpw4<<<(n4+255)/256, 256>>>(xpw, xpwh);
    }

    // ---- prepend MLP: p = silu(pc @ w1) @ w2 (fp32) ----
    zero_kernel<<<(128*D_+255)/256, 256>>>(p1, 128*D_);
    gemm_f32<64,64,16,4,4><<<dim3(2,16,3), 256>>>(pc, PCD_, w1, p1, 128, D_, PCD_);
    silu_kernel<<<(128*D_+255)/256, 256>>>(p1, 128*D_);
    zero_kernel<<<(128*D_+255)/256, 256>>>(p2, 128*D_);
    gemm_f32<64,64,16,4,4><<<dim3(2,16,4), 256>>>(p1, D_, w2, p2, 128, D_, D_);
    build_h_kernel<<<(M_*D_+255)/256, 256>>>(p2, x, h);

    // ---- 4 mamba layers ----
    for (int l = 0; l < L_; l++) {
        rmsnorm_split_kernel<<<M_, 256>>>(h, norm_w + (size_t)l*D_, xnh, xnl);

        // xz = xn @ in_proj_w^T   [1152,1024] x [4096,1024]^T   (576 CTAs)
        tc_gemm<0><<<dim3(18, 32, 1), 128, GEMM_DYN>>>(
            xnh, xnl, ipwh + (size_t)l*2*DI_*D_,
            nullptr, xzp, D_, 2*DI_, 2*DI_);

        // conv + silu + xi splits (+ zero xdbl for the split-K below)
        conv_silu4<<<(M_*(DI_/4)+255)/256, 256>>>(
            xzp, cw + (size_t)l*DI_*4, cb + (size_t)l*DI_, xip, xih, xil, xdblp);

        // xdbl = xi @ x_proj_w^T  [1152,2048] x [96(pad128),2048]^T  split-K=16
        tc_gemm<1><<<dim3(18, 1, 16), 128, GEMM_DYN>>>(
            xih, xil, xpwh + (size_t)l*128*DI_,
            nullptr, xdblp, DI_, 96, 96);

        split_dtr4<<<(M_*(DR_/4)+255)/256, 256>>>(xdblp, dtrh, dtrl);

        // dt = softplus(dtr @ dt_proj_w^T + b)  [1152,64] x [2048,64]^T
        tc_gemm<2><<<dim3(18, 16, 1), 128, GEMM_DYN>>>(
            dtrh, dtrl, dtwh + (size_t)l*DI_*DR_,
            dtb + (size_t)l*DI_, dtp, DR_, DI_, DI_);

        // selective scan + gate -> y splits
        scan_kernel<<<(B_*DI_/2)/4, 128>>>(
            xzp, xip, xdblp, dtp,
            A_log + (size_t)l*DI_*DS_, Dparam + (size_t)l*DI_, yh, yl);

        // h += y @ out_proj_w^T   [1152,2048] x [1024,2048]^T  split-K=4 (576 CTAs)
        tc_gemm<1><<<dim3(18, 8, 4), 128, GEMM_DYN>>>(
            yh, yl, opwh + (size_t)l*D_*DI_,
            nullptr, h, DI_, D_, D_);
    }

    // ---- final rmsnorm + slice ----
    final_kernel<<<B_*S_, 256>>>(h, fnw, (float*)d_out);
}

// round 6
// speedup vs baseline: 3.2411x; 1.3056x over previous
#include <cuda_runtime.h>
#include <cuda_bf16.h>
#include <math.h>
#include <stdint.h>

#define B_   2
#define S_   512
#define P_   64
#define T_   576
#define D_   1024
#define L_   4
#define DI_  2048
#define DS_  16
#define DR_  64
#define PCD_ 768
#define M_   (B_*T_)   // 1152

// ---------------- static scratch ----------------
__device__ float g_h   [M_*D_];
__device__ float g_xz  [M_*2*DI_];
__device__ float g_xi  [M_*DI_];
__device__ float g_dt  [M_*DI_];
__device__ float g_xdbl[M_*96];
__device__ float g_p1  [128*D_];
__device__ float g_p2  [128*D_];

__device__ __align__(16) __nv_bfloat16 g_xn_h [M_*D_];
__device__ __align__(16) __nv_bfloat16 g_xi_h [M_*DI_];
__device__ __align__(16) __nv_bfloat16 g_y_h  [M_*DI_];
__device__ __align__(16) __nv_bfloat16 g_dtr_h[M_*DR_];

// weights: bf16
__device__ __align__(16) __nv_bfloat16 g_ipw_h[L_*2*DI_*D_];
__device__ __align__(16) __nv_bfloat16 g_opw_h[L_*D_*DI_];
__device__ __align__(16) __nv_bfloat16 g_xpw_h[L_*128*DI_];   // N padded 96->128
__device__ __align__(16) __nv_bfloat16 g_dtw_h[L_*DI_*DR_];

// ---------------- helpers ----------------
__device__ __forceinline__ float siluf(float x) { return x / (1.f + __expf(-x)); }
__device__ __forceinline__ float softplusf(float x) {
    return x > 20.f ? x : log1pf(__expf(x));
}
__device__ __forceinline__ uint32_t smem_u32(const void* p) {
    uint32_t a;
    asm("{ .reg .u64 t; cvta.to.shared.u64 t, %1; cvt.u32.u64 %0, t; }" : "=r"(a) : "l"(p));
    return a;
}
__device__ __forceinline__ uint32_t pack2(float a, float b) {
    __nv_bfloat162 t = __floats2bfloat162_rn(a, b);
    return *(uint32_t*)&t;
}
__device__ __forceinline__ void cvt_store4(float4 v, __nv_bfloat16* __restrict__ hp, size_t i4) {
    uint2 o;
    o.x = pack2(v.x, v.y);
    o.y = pack2(v.z, v.w);
    ((uint2*)hp)[i4] = o;
}

// ---------------- async copy / ldmatrix / mma primitives ----------------
__device__ __forceinline__ void cp16(uint32_t s, const void* g) {
    asm volatile("cp.async.ca.shared.global [%0], [%1], 16;" :: "r"(s), "l"(g));
}
__device__ __forceinline__ void cp_commit() {
    asm volatile("cp.async.commit_group;" ::: "memory");
}
template<int N>
__device__ __forceinline__ void cp_wait() {
    asm volatile("cp.async.wait_group %0;" :: "n"(N) : "memory");
}
#define LDSM4(r0,r1,r2,r3,addr) \
    asm volatile("ldmatrix.sync.aligned.m8n8.x4.shared.b16 {%0,%1,%2,%3}, [%4];" \
        : "=r"(r0),"=r"(r1),"=r"(r2),"=r"(r3) : "r"(addr))

__device__ __forceinline__ void mma16816(float* c, const uint32_t* a, const uint32_t* b) {
    asm volatile(
        "mma.sync.aligned.m16n8k16.row.col.f32.bf16.bf16.f32 "
        "{%0,%1,%2,%3}, {%4,%5,%6,%7}, {%8,%9}, {%0,%1,%2,%3};"
        : "+f"(c[0]), "+f"(c[1]), "+f"(c[2]), "+f"(c[3])
        : "r"(a[0]), "r"(a[1]), "r"(a[2]), "r"(a[3]), "r"(b[0]), "r"(b[1]));
}

// swizzled byte offset within a tile: row pitch 64B (32 bf16), 16B chunks
__device__ __forceinline__ uint32_t soff(int r, int ch) {
    return (uint32_t)(r * 64 + ((ch ^ ((r >> 1) & 3)) << 4));
}

// ---------------- pipelined bf16 tensor-core GEMM (single pass) ----------------
// C[M x NC] (+)= Ah[M,K] * Bh[N,K]^T   (both bf16)
// BM=64, BN=128, BK=32, 128 threads (4 warps 2x2), warp tile 32x64.
// 4-stage cp.async pipeline, single __syncthreads per iteration.
// EPI: 0 = store, 1 = atomicAdd (masked n<NC), 2 = softplus(v+bias[n]) store.
#define STAGE_BYTES 12288   // AH 4K | BH 8K
#define NSTAGE 4
#define GEMM_DYN (NSTAGE*STAGE_BYTES + 128)

template<int EPI>
__global__ void __launch_bounds__(128, 3)
tc_gemm(const __nv_bfloat16* __restrict__ Ah,
        const __nv_bfloat16* __restrict__ Bh,
        const float* __restrict__ bias, float* __restrict__ C,
        int K, int NC, int ldc)
{
    extern __shared__ __align__(16) char dsm[];
    const uint32_t sb = (smem_u32(dsm) + 127u) & ~127u;

    const int tid  = threadIdx.x;
    const int lane = tid & 31;
    const int wid  = tid >> 5;
    const int wm   = wid >> 1;           // 0..1
    const int wn   = wid & 1;            // 0..1
    const int m0   = blockIdx.x * 64;
    const int n0   = blockIdx.y * 128;
    const int kPer = K / gridDim.z;
    const int kBeg = blockIdx.z * kPer;
    const int nIter = kPer >> 5;         // BK=32

    const __nv_bfloat16* gAh = Ah + (size_t)m0 * K + kBeg;
    const __nv_bfloat16* gBh = Bh + (size_t)n0 * K + kBeg;

    const int sr = tid >> 2;             // 0..31
    const int sc = tid & 3;              // 0..3

    auto load_stage = [&](int slot, int kof) {
        const uint32_t st = sb + slot * STAGE_BYTES;
        #pragma unroll
        for (int p = 0; p < 2; p++) {
            int r = sr + p * 32;
            cp16(st + soff(r, sc), gAh + (size_t)r * K + kof + sc * 8);
        }
        #pragma unroll
        for (int p = 0; p < 4; p++) {
            int r = sr + p * 32;
            cp16(st + 4096 + soff(r, sc), gBh + (size_t)r * K + kof + sc * 8);
        }
    };

    float acc[2][8][4];
    #pragma unroll
    for (int mi = 0; mi < 2; mi++)
        #pragma unroll
        for (int ni = 0; ni < 8; ni++)
            #pragma unroll
            for (int q = 0; q < 4; q++) acc[mi][ni][q] = 0.f;

    #pragma unroll
    for (int s = 0; s < NSTAGE - 1; s++) {
        if (s < nIter) load_stage(s, s * 32);
        cp_commit();
    }

    const int g  = lane >> 3;
    const int lr = lane & 7;

    for (int it = 0; it < nIter; it++) {
        cp_wait<NSTAGE - 2>();
        __syncthreads();
        int ns = it + NSTAGE - 1;
        if (ns < nIter) load_stage(ns & 3, ns * 32);
        cp_commit();

        const uint32_t st = sb + (it & 3) * STAGE_BYTES;
        #pragma unroll
        for (int ks = 0; ks < 2; ks++) {
            const int kc8 = ks * 2;
            uint32_t aH[2][4], bH[8][2];
            #pragma unroll
            for (int mi = 0; mi < 2; mi++) {
                int r  = wm * 32 + mi * 16 + (g & 1) * 8 + lr;
                int ch = kc8 + (g >> 1);
                uint32_t ad = st + soff(r, ch);
                LDSM4(aH[mi][0], aH[mi][1], aH[mi][2], aH[mi][3], ad);
            }
            #pragma unroll
            for (int t = 0; t < 4; t++) {
                int r  = wn * 64 + t * 16 + (g >> 1) * 8 + lr;
                int ch = kc8 + (g & 1);
                uint32_t ad = st + 4096 + soff(r, ch);
                LDSM4(bH[2*t][0], bH[2*t][1], bH[2*t+1][0], bH[2*t+1][1], ad);
            }
            #pragma unroll
            for (int mi = 0; mi < 2; mi++)
                #pragma unroll
                for (int ni = 0; ni < 8; ni++) mma16816(acc[mi][ni], aH[mi], bH[ni]);
        }
    }

    // epilogue
    #pragma unroll
    for (int mi = 0; mi < 2; mi++) {
        #pragma unroll
        for (int ni = 0; ni < 8; ni++) {
            int r  = m0 + wm * 32 + mi * 16 + (lane >> 2);
            int cc = n0 + wn * 64 + ni * 8 + (lane & 3) * 2;
            #pragma unroll
            for (int half = 0; half < 2; half++) {
                int rr = r + half * 8;
                float v0 = acc[mi][ni][half * 2];
                float v1 = acc[mi][ni][half * 2 + 1];
                if (EPI == 2) {
                    v0 = softplusf(v0 + bias[cc]);
                    v1 = softplusf(v1 + bias[cc + 1]);
                }
                size_t o = (size_t)rr * ldc + cc;
                if (EPI == 1) {
                    if (cc < NC)     atomicAdd(&C[o], v0);
                    if (cc + 1 < NC) atomicAdd(&C[o + 1], v1);
                } else {
                    *(float2*)(C + o) = make_float2(v0, v1);
                }
            }
        }
    }
}

// ---------------- fp32 split-K GEMM (prepend MLP only) ----------------
template<int BM, int BN, int BK, int TM, int TN>
__launch_bounds__((BM/TM)*(BN/TN), 2)
__global__ void gemm_f32(const float* __restrict__ Ap, int lda,
                         const float* __restrict__ Bp,
                         float* __restrict__ Cp,
                         int M, int N, int K) {
    constexpr int THREADS = (BM/TM)*(BN/TN);
    __shared__ float As[BK][BM];
    __shared__ float Bs[BK][BN];
    const int tid = threadIdx.x;
    const int tx  = tid % (BN/TN);
    const int ty  = tid / (BN/TN);
    const int m0  = blockIdx.x * BM;
    const int n0  = blockIdx.y * BN;
    int kl = K / gridDim.z;
    int kBeg = blockIdx.z * kl, kEnd = kBeg + kl;

    float acc[TM][TN];
    #pragma unroll
    for (int i = 0; i < TM; i++)
        #pragma unroll
        for (int j = 0; j < TN; j++) acc[i][j] = 0.f;

    for (int k0 = kBeg; k0 < kEnd; k0 += BK) {
        #pragma unroll
        for (int i = tid; i < BM*BK/4; i += THREADS) {
            int row = i / (BK/4);
            int kc  = (i % (BK/4)) * 4;
            float4 v = make_float4(0.f,0.f,0.f,0.f);
            if (m0 + row < M)
                v = *(const float4*)(Ap + (size_t)(m0+row)*lda + k0 + kc);
            As[kc+0][row] = v.x; As[kc+1][row] = v.y;
            As[kc+2][row] = v.z; As[kc+3][row] = v.w;
        }
        #pragma unroll
        for (int i = tid; i < BK*BN/4; i += THREADS) {
            int kr = i / (BN/4);
            int nc = (i % (BN/4)) * 4;
            float4 v = *(const float4*)(Bp + (size_t)(k0+kr)*N + n0 + nc);
            *(float4*)&Bs[kr][nc] = v;
        }
        __syncthreads();
        #pragma unroll
        for (int kk = 0; kk < BK; kk++) {
            float a[TM], b[TN];
            #pragma unroll
            for (int i = 0; i < TM; i += 4)
                *(float4*)&a[i] = *(const float4*)&As[kk][ty*TM + i];
            #pragma unroll
            for (int j = 0; j < TN; j += 4)
                *(float4*)&b[j] = *(const float4*)&Bs[kk][tx*TN + j];
            #pragma unroll
            for (int i = 0; i < TM; i++)
                #pragma unroll
                for (int j = 0; j < TN; j++)
                    acc[i][j] = fmaf(a[i], b[j], acc[i][j]);
        }
        __syncthreads();
    }
    #pragma unroll
    for (int i = 0; i < TM; i++) {
        int m = m0 + ty*TM + i;
        if (m >= M) continue;
        #pragma unroll
        for (int j = 0; j < TN; j++) {
            int n = n0 + tx*TN + j;
            atomicAdd(&Cp[(size_t)m*N + n], acc[i][j]);
        }
    }
}

// ---------------- convert / prep kernels ----------------
__global__ void convert_w4(const float* __restrict__ in,
                           __nv_bfloat16* __restrict__ h, int n4) {
    int i = blockIdx.x * 256 + threadIdx.x;
    if (i >= n4) return;
    cvt_store4(((const float4*)in)[i], h, i);
}

__global__ void convert_xpw4(const float* __restrict__ in,
                             __nv_bfloat16* __restrict__ h) {
    int i = blockIdx.x * 256 + threadIdx.x;
    if (i >= L_ * 128 * (DI_/4)) return;
    int k4   = i % (DI_/4);
    int nrow = (i / (DI_/4)) % 128;
    int lay  = i / (128 * (DI_/4));
    float4 v = make_float4(0.f, 0.f, 0.f, 0.f);
    if (nrow < 96)
        v = ((const float4*)in)[(size_t)(lay * 96 + nrow) * (DI_/4) + k4];
    cvt_store4(v, h, i);
}

__global__ void split_dtr4(const float* __restrict__ xdbl,
                           __nv_bfloat16* __restrict__ h) {
    int i = blockIdx.x * 256 + threadIdx.x;
    if (i >= M_ * (DR_/4)) return;
    int m = i / (DR_/4), c4 = i % (DR_/4);
    cvt_store4(((const float4*)xdbl)[(size_t)m * 24 + c4], h, i);
}

__global__ void zero_kernel(float* __restrict__ p, int n) {
    int i = blockIdx.x * blockDim.x + threadIdx.x;
    if (i < n) p[i] = 0.f;
}

__global__ void silu_kernel(float* __restrict__ p, int n) {
    int i = blockIdx.x * blockDim.x + threadIdx.x;
    if (i < n) p[i] = siluf(p[i]);
}

__global__ void build_h_kernel(const float* __restrict__ p,
                               const float* __restrict__ x,
                               float* __restrict__ h) {
    int idx = blockIdx.x * blockDim.x + threadIdx.x;
    if (idx >= M_*D_) return;
    int d = idx % D_;
    int m = idx / D_;
    int b = m / T_;
    int t = m % T_;
    h[idx] = (t < P_) ? p[(size_t)(b*P_ + t)*D_ + d]
                      : x[(size_t)(b*S_ + (t - P_))*D_ + d];
}

__global__ void rmsnorm_bf16_kernel(const float* __restrict__ in,
                                    const float* __restrict__ w,
                                    __nv_bfloat16* __restrict__ oh) {
    int row = blockIdx.x;
    int tid = threadIdx.x;
    const float4* r = (const float4*)(in + (size_t)row*D_);
    float4 x4 = r[tid];
    float s = x4.x*x4.x + x4.y*x4.y + x4.z*x4.z + x4.w*x4.w;
    #pragma unroll
    for (int o = 16; o; o >>= 1) s += __shfl_xor_sync(0xffffffffu, s, o);
    __shared__ float ws[8];
    __shared__ float scale_s;
    if ((tid & 31) == 0) ws[tid >> 5] = s;
    __syncthreads();
    if (tid == 0) {
        float t = 0.f;
        #pragma unroll
        for (int i = 0; i < 8; i++) t += ws[i];
        scale_s = rsqrtf(t / (float)D_ + 1e-5f);
    }
    __syncthreads();
    float sc = scale_s;
    float4 wv = ((const float4*)w)[tid];
    float4 v = make_float4(x4.x*sc*wv.x, x4.y*sc*wv.y, x4.z*sc*wv.z, x4.w*sc*wv.w);
    cvt_store4(v, oh, (size_t)row*(D_/4) + tid);
}

__global__ void final_kernel(const float* __restrict__ hin,
                             const float* __restrict__ w,
                             float* __restrict__ out) {
    int row = blockIdx.x;
    int b = row >> 9;
    int t = row & 511;
    int hrow = b*T_ + P_ + t;
    int tid = threadIdx.x;
    const float4* r = (const float4*)(hin + (size_t)hrow*D_);
    float4 x4 = r[tid];
    float s = x4.x*x4.x + x4.y*x4.y + x4.z*x4.z + x4.w*x4.w;
    #pragma unroll
    for (int o = 16; o; o >>= 1) s += __shfl_xor_sync(0xffffffffu, s, o);
    __shared__ float ws[8];
    __shared__ float scale_s;
    if ((tid & 31) == 0) ws[tid >> 5] = s;
    __syncthreads();
    if (tid == 0) {
        float tt = 0.f;
        #pragma unroll
        for (int i = 0; i < 8; i++) tt += ws[i];
        scale_s = rsqrtf(tt / (float)D_ + 1e-5f);
    }
    __syncthreads();
    float sc = scale_s;
    float4 wv = ((const float4*)w)[tid];
    float4 o4 = make_float4(x4.x*sc*wv.x, x4.y*sc*wv.y, x4.z*sc*wv.z, x4.w*sc*wv.w);
    ((float4*)(out + (size_t)row*D_))[tid] = o4;
}

// depthwise causal conv (DC=4) + silu, 4 channels/thread; zeroes xdbl
__global__ void conv_silu4(const float* __restrict__ xz,
                           const float* __restrict__ cw,
                           const float* __restrict__ cb,
                           float* __restrict__ xi,
                           __nv_bfloat16* __restrict__ xih,
                           float* __restrict__ xdbl) {
    int idx = blockIdx.x * blockDim.x + threadIdx.x;
    if (idx >= M_*(DI_/4)) return;
    if (idx < M_*96/4) ((float4*)xdbl)[idx] = make_float4(0.f,0.f,0.f,0.f);

    int e4 = idx % (DI_/4);
    int m  = idx / (DI_/4);
    int t  = m % T_;
    float4 w0 = ((const float4*)cw)[e4*4+0];
    float4 w1 = ((const float4*)cw)[e4*4+1];
    float4 w2 = ((const float4*)cw)[e4*4+2];
    float4 w3 = ((const float4*)cw)[e4*4+3];
    float4 acc = ((const float4*)cb)[e4];
    const float* wj[4] = { (const float*)&w0, (const float*)&w1,
                           (const float*)&w2, (const float*)&w3 };
    #pragma unroll
    for (int j = 0; j < 4; j++) {
        int tt = t - 3 + j;
        if (tt >= 0) {
            float4 xv = ((const float4*)(xz + (size_t)(m - 3 + j)*(2*DI_)))[e4];
            acc.x = fmaf(xv.x, wj[0][j], acc.x);
            acc.y = fmaf(xv.y, wj[1][j], acc.y);
            acc.z = fmaf(xv.z, wj[2][j], acc.z);
            acc.w = fmaf(xv.w, wj[3][j], acc.w);
        }
    }
    float4 v = make_float4(siluf(acc.x), siluf(acc.y), siluf(acc.z), siluf(acc.w));
    ((float4*)xi)[idx] = v;
    cvt_store4(v, xih, idx);
}

// selective scan: warp = 2 channels x 16 states; 8-timestep batches.
__global__ void scan_kernel(const float* __restrict__ xz,
                            const float* __restrict__ xi,
                            const float* __restrict__ xdbl,
                            const float* __restrict__ dt,
                            const float* __restrict__ A_log,
                            const float* __restrict__ Dp,
                            __nv_bfloat16* __restrict__ yh) {
    int lane = threadIdx.x & 31;
    int warp = threadIdx.x >> 5;
    int pair = blockIdx.x * 4 + warp;
    int b = pair >> 10;
    int e = ((pair & 1023) << 1) + (lane >> 4);
    int s = lane & 15;

    float A  = -expf(A_log[(size_t)e*DS_ + s]);
    float Dv = Dp[e];
    float h  = 0.f;
    int m0 = b * T_;

    const float* dt_p = dt   + (size_t)m0*DI_ + e;
    const float* xi_p = xi   + (size_t)m0*DI_ + e;
    const float* z_p  = xz   + (size_t)m0*(2*DI_) + DI_ + e;
    const float* bc_p = xdbl + (size_t)m0*96 + DR_ + s;
    size_t ybase = (size_t)m0*DI_ + (e & ~1);

    for (int tb = 0; tb < T_; tb += 8) {
        float dtv[8], xiv[8], Bv[8], Cv[8], zv[8];
        #pragma unroll
        for (int j = 0; j < 8; j++) {
            size_t t = tb + j;
            dtv[j] = dt_p[t*DI_];
            xiv[j] = xi_p[t*DI_];
            zv[j]  = z_p [t*(2*DI_)];
            Bv[j]  = bc_p[t*96];
            Cv[j]  = bc_p[t*96 + 16];
        }
        float p[8];
        #pragma unroll
        for (int j = 0; j < 8; j++) {
            float dA = __expf(dtv[j] * A);
            h = fmaf(dA, h, dtv[j] * Bv[j] * xiv[j]);
            p[j] = h * Cv[j];
        }
        #pragma unroll
        for (int o = 8; o >= 1; o >>= 1)
            #pragma unroll
            for (int j = 0; j < 8; j++)
                p[j] += __shfl_xor_sync(0xffffffffu, p[j], o);
        #pragma unroll
        for (int j = 0; j < 8; j++) {
            float val = (p[j] + xiv[j] * Dv) * siluf(zv[j]);
            float v1  = __shfl_down_sync(0xffffffffu, val, 16);
            if (lane == 0) {
                size_t o2 = (ybase + (size_t)(tb + j) * DI_) >> 1;
                ((uint32_t*)yh)[o2] = pack2(val, v1);
            }
        }
    }
}

// ---------------- host orchestration ----------------
extern "C" void kernel_launch(void* const* d_in, const int* in_sizes, int n_in,
                              void* d_out, int out_size) {
    (void)in_sizes; (void)n_in; (void)out_size;
    const float* x      = (const float*)d_in[0];
    const float* pc     = (const float*)d_in[1];
    const float* w1     = (const float*)d_in[2];
    const float* w2     = (const float*)d_in[3];
    const float* norm_w = (const float*)d_in[4];
    const float* ipw    = (const float*)d_in[5];
    const float* cw     = (const float*)d_in[6];
    const float* cb     = (const float*)d_in[7];
    const float* xpw    = (const float*)d_in[8];
    const float* dtw    = (const float*)d_in[9];
    const float* dtb    = (const float*)d_in[10];
    const float* A_log  = (const float*)d_in[11];
    const float* Dparam = (const float*)d_in[12];
    const float* opw    = (const float*)d_in[13];
    const float* fnw    = (const float*)d_in[14];

    float *h, *xzp, *xip, *dtp, *xdblp, *p1, *p2;
    cudaGetSymbolAddress((void**)&h,     g_h);
    cudaGetSymbolAddress((void**)&xzp,   g_xz);
    cudaGetSymbolAddress((void**)&xip,   g_xi);
    cudaGetSymbolAddress((void**)&dtp,   g_dt);
    cudaGetSymbolAddress((void**)&xdblp, g_xdbl);
    cudaGetSymbolAddress((void**)&p1,    g_p1);
    cudaGetSymbolAddress((void**)&p2,    g_p2);

    __nv_bfloat16 *xnh, *xih, *yh, *dtrh, *ipwh, *opwh, *xpwh, *dtwh;
    cudaGetSymbolAddress((void**)&xnh,  g_xn_h);
    cudaGetSymbolAddress((void**)&xih,  g_xi_h);
    cudaGetSymbolAddress((void**)&yh,   g_y_h);
    cudaGetSymbolAddress((void**)&dtrh, g_dtr_h);
    cudaGetSymbolAddress((void**)&ipwh, g_ipw_h);
    cudaGetSymbolAddress((void**)&opwh, g_opw_h);
    cudaGetSymbolAddress((void**)&xpwh, g_xpw_h);
    cudaGetSymbolAddress((void**)&dtwh, g_dtw_h);

    cudaFuncSetAttribute(tc_gemm<0>, cudaFuncAttributeMaxDynamicSharedMemorySize, GEMM_DYN);
    cudaFuncSetAttribute(tc_gemm<1>, cudaFuncAttributeMaxDynamicSharedMemorySize, GEMM_DYN);
    cudaFuncSetAttribute(tc_gemm<2>, cudaFuncAttributeMaxDynamicSharedMemorySize, GEMM_DYN);

    // ---- weight converts (fp32 -> bf16, vectorized) ----
    {
        int n4;
        n4 = L_*2*DI_*D_/4; convert_w4<<<(n4+255)/256, 256>>>(ipw, ipwh, n4);
        n4 = L_*D_*DI_/4;   convert_w4<<<(n4+255)/256, 256>>>(opw, opwh, n4);
        n4 = L_*DI_*DR_/4;  convert_w4<<<(n4+255)/256, 256>>>(dtw, dtwh, n4);
        n4 = L_*128*DI_/4;  convert_xpw4<<<(n4+255)/256, 256>>>(xpw, xpwh);
    }

    // ---- prepend MLP: p = silu(pc @ w1) @ w2 (fp32, deeper split-K) ----
    zero_kernel<<<(128*D_+255)/256, 256>>>(p1, 128*D_);
    gemm_f32<64,64,16,4,4><<<dim3(2,16,6), 256>>>(pc, PCD_, w1, p1, 128, D_, PCD_);
    silu_kernel<<<(128*D_+255)/256, 256>>>(p1, 128*D_);
    zero_kernel<<<(128*D_+255)/256, 256>>>(p2, 128*D_);
    gemm_f32<64,64,16,4,4><<<dim3(2,16,8), 256>>>(p1, D_, w2, p2, 128, D_, D_);
    build_h_kernel<<<(M_*D_+255)/256, 256>>>(p2, x, h);

    // ---- 4 mamba layers ----
    for (int l = 0; l < L_; l++) {
        rmsnorm_bf16_kernel<<<M_, 256>>>(h, norm_w + (size_t)l*D_, xnh);

        // xz = xn @ in_proj_w^T   [1152,1024] x [4096,1024]^T   (576 CTAs)
        tc_gemm<0><<<dim3(18, 32, 1), 128, GEMM_DYN>>>(
            xnh, ipwh + (size_t)l*2*DI_*D_, nullptr, xzp, D_, 2*DI_, 2*DI_);

        conv_silu4<<<(M_*(DI_/4)+255)/256, 256>>>(
            xzp, cw + (size_t)l*DI_*4, cb + (size_t)l*DI_, xip, xih, xdblp);

        // xdbl = xi @ x_proj_w^T  [1152,2048] x [96(pad128),2048]^T  split-K=8 (144 CTAs)
        tc_gemm<1><<<dim3(18, 1, 8), 128, GEMM_DYN>>>(
            xih, xpwh + (size_t)l*128*DI_, nullptr, xdblp, DI_, 96, 96);

        split_dtr4<<<(M_*(DR_/4)+255)/256, 256>>>(xdblp, dtrh);

        // dt = softplus(dtr @ dt_proj_w^T + b)  [1152,64] x [2048,64]^T  (288 CTAs)
        tc_gemm<2><<<dim3(18, 16, 1), 128, GEMM_DYN>>>(
            dtrh, dtwh + (size_t)l*DI_*DR_, dtb + (size_t)l*DI_, dtp, DR_, DI_, DI_);

        // selective scan + gate -> y bf16
        scan_kernel<<<(B_*DI_/2)/4, 128>>>(
            xzp, xip, xdblp, dtp,
            A_log + (size_t)l*DI_*DS_, Dparam + (size_t)l*DI_, yh);

        // h += y @ out_proj_w^T   [1152,2048] x [1024,2048]^T  split-K=2 (288 CTAs)
        tc_gemm<1><<<dim3(18, 8, 2), 128, GEMM_DYN>>>(
            yh, opwh + (size_t)l*D_*DI_, nullptr, h, DI_, D_, D_);
    }

    // ---- final rmsnorm + slice ----
    final_kernel<<<B_*S_, 256>>>(h, fnw, (float*)d_out);
}

// round 7
// speedup vs baseline: 3.3093x; 1.0210x over previous
#include <cuda_runtime.h>
#include <cuda_bf16.h>
#include <math.h>
#include <stdint.h>

#define B_   2
#define S_   512
#define P_   64
#define T_   576
#define D_   1024
#define L_   4
#define DI_  2048
#define DS_  16
#define DR_  64
#define PCD_ 768
#define M_   (B_*T_)   // 1152

// ---------------- static scratch ----------------
__device__ float g_h   [M_*D_];
__device__ float g_xz  [M_*2*DI_];
__device__ float g_xi  [M_*DI_];
__device__ float g_dt  [M_*DI_];
__device__ float g_xdbl[M_*96];
__device__ float g_p1  [128*D_];
__device__ float g_p2  [128*D_];

__device__ __align__(16) __nv_bfloat16 g_xn_h [M_*D_];
__device__ __align__(16) __nv_bfloat16 g_xi_h [M_*DI_];
__device__ __align__(16) __nv_bfloat16 g_y_h  [M_*DI_];

// weights: bf16
__device__ __align__(16) __nv_bfloat16 g_ipw_h[L_*2*DI_*D_];
__device__ __align__(16) __nv_bfloat16 g_opw_h[L_*D_*DI_];
__device__ __align__(16) __nv_bfloat16 g_xpw_h[L_*128*DI_];   // N padded 96->128
__device__ __align__(16) __nv_bfloat16 g_dtw_h[L_*DI_*DR_];

// ---------------- helpers ----------------
__device__ __forceinline__ float siluf(float x) { return x / (1.f + __expf(-x)); }
__device__ __forceinline__ float softplusf(float x) {
    return x > 20.f ? x : log1pf(__expf(x));
}
__device__ __forceinline__ uint32_t smem_u32(const void* p) {
    uint32_t a;
    asm("{ .reg .u64 t; cvta.to.shared.u64 t, %1; cvt.u32.u64 %0, t; }" : "=r"(a) : "l"(p));
    return a;
}
__device__ __forceinline__ uint32_t pack2(float a, float b) {
    __nv_bfloat162 t = __floats2bfloat162_rn(a, b);
    return *(uint32_t*)&t;
}
__device__ __forceinline__ void cvt_store4(float4 v, __nv_bfloat16* __restrict__ hp, size_t i4) {
    uint2 o;
    o.x = pack2(v.x, v.y);
    o.y = pack2(v.z, v.w);
    ((uint2*)hp)[i4] = o;
}

// ---------------- async copy / ldmatrix / mma primitives ----------------
__device__ __forceinline__ void cp16(uint32_t s, const void* g) {
    asm volatile("cp.async.ca.shared.global [%0], [%1], 16;" :: "r"(s), "l"(g));
}
__device__ __forceinline__ void cp_commit() {
    asm volatile("cp.async.commit_group;" ::: "memory");
}
template<int N>
__device__ __forceinline__ void cp_wait() {
    asm volatile("cp.async.wait_group %0;" :: "n"(N) : "memory");
}
#define LDSM4(r0,r1,r2,r3,addr) \
    asm volatile("ldmatrix.sync.aligned.m8n8.x4.shared.b16 {%0,%1,%2,%3}, [%4];" \
        : "=r"(r0),"=r"(r1),"=r"(r2),"=r"(r3) : "r"(addr))

__device__ __forceinline__ void mma16816(float* c, const uint32_t* a, const uint32_t* b) {
    asm volatile(
        "mma.sync.aligned.m16n8k16.row.col.f32.bf16.bf16.f32 "
        "{%0,%1,%2,%3}, {%4,%5,%6,%7}, {%8,%9}, {%0,%1,%2,%3};"
        : "+f"(c[0]), "+f"(c[1]), "+f"(c[2]), "+f"(c[3])
        : "r"(a[0]), "r"(a[1]), "r"(a[2]), "r"(a[3]), "r"(b[0]), "r"(b[1]));
}

// swizzled byte offset within a tile: row pitch 64B (32 bf16), 16B chunks
__device__ __forceinline__ uint32_t soff(int r, int ch) {
    return (uint32_t)(r * 64 + ((ch ^ ((r >> 1) & 3)) << 4));
}

// ---------------- pipelined bf16 tensor-core GEMM ----------------
// C[M x NC] (+)= Ah[M,K] * Bh[N,K]^T   (both bf16)
// BM=128, BN=128, BK=32, 256 threads (8 warps 4x2), warp tile 32x64.
// 4-stage cp.async pipeline, single __syncthreads per iteration.
// EPI: 0 = store, 1 = atomicAdd (masked n<NC)
#define STAGE_BYTES 16384   // AH 8K | BH 8K
#define NSTAGE 4
#define GEMM_DYN (NSTAGE*STAGE_BYTES + 128)

template<int EPI>
__global__ void __launch_bounds__(256, 2)
tc_gemm(const __nv_bfloat16* __restrict__ Ah,
        const __nv_bfloat16* __restrict__ Bh,
        float* __restrict__ C,
        int K, int NC, int ldc)
{
    extern __shared__ __align__(16) char dsm[];
    const uint32_t sb = (smem_u32(dsm) + 127u) & ~127u;

    const int tid  = threadIdx.x;
    const int lane = tid & 31;
    const int wid  = tid >> 5;
    const int wm   = wid >> 1;           // 0..3
    const int wn   = wid & 1;            // 0..1
    const int m0   = blockIdx.x * 128;
    const int n0   = blockIdx.y * 128;
    const int kPer = K / gridDim.z;
    const int kBeg = blockIdx.z * kPer;
    const int nIter = kPer >> 5;         // BK=32

    const __nv_bfloat16* gAh = Ah + (size_t)m0 * K + kBeg;
    const __nv_bfloat16* gBh = Bh + (size_t)n0 * K + kBeg;

    const int sr = tid >> 2;             // 0..63
    const int sc = tid & 3;              // 0..3

    auto load_stage = [&](int slot, int kof) {
        const uint32_t st = sb + slot * STAGE_BYTES;
        #pragma unroll
        for (int p = 0; p < 2; p++) {
            int r = sr + p * 64;
            cp16(st + soff(r, sc), gAh + (size_t)r * K + kof + sc * 8);
        }
        #pragma unroll
        for (int p = 0; p < 2; p++) {
            int r = sr + p * 64;
            cp16(st + 8192 + soff(r, sc), gBh + (size_t)r * K + kof + sc * 8);
        }
    };

    float acc[2][8][4];
    #pragma unroll
    for (int mi = 0; mi < 2; mi++)
        #pragma unroll
        for (int ni = 0; ni < 8; ni++)
            #pragma unroll
            for (int q = 0; q < 4; q++) acc[mi][ni][q] = 0.f;

    #pragma unroll
    for (int s = 0; s < NSTAGE - 1; s++) {
        if (s < nIter) load_stage(s, s * 32);
        cp_commit();
    }

    const int g  = lane >> 3;
    const int lr = lane & 7;

    for (int it = 0; it < nIter; it++) {
        cp_wait<NSTAGE - 2>();
        __syncthreads();
        int ns = it + NSTAGE - 1;
        if (ns < nIter) load_stage(ns & 3, ns * 32);
        cp_commit();

        const uint32_t st = sb + (it & 3) * STAGE_BYTES;
        #pragma unroll
        for (int ks = 0; ks < 2; ks++) {
            const int kc8 = ks * 2;
            uint32_t aH[2][4], bH[8][2];
            #pragma unroll
            for (int mi = 0; mi < 2; mi++) {
                int r  = wm * 32 + mi * 16 + (g & 1) * 8 + lr;
                int ch = kc8 + (g >> 1);
                uint32_t ad = st + soff(r, ch);
                LDSM4(aH[mi][0], aH[mi][1], aH[mi][2], aH[mi][3], ad);
            }
            #pragma unroll
            for (int t = 0; t < 4; t++) {
                int r  = wn * 64 + t * 16 + (g >> 1) * 8 + lr;
                int ch = kc8 + (g & 1);
                uint32_t ad = st + 8192 + soff(r, ch);
                LDSM4(bH[2*t][0], bH[2*t][1], bH[2*t+1][0], bH[2*t+1][1], ad);
            }
            #pragma unroll
            for (int mi = 0; mi < 2; mi++)
                #pragma unroll
                for (int ni = 0; ni < 8; ni++) mma16816(acc[mi][ni], aH[mi], bH[ni]);
        }
    }

    // epilogue
    #pragma unroll
    for (int mi = 0; mi < 2; mi++) {
        #pragma unroll
        for (int ni = 0; ni < 8; ni++) {
            int r  = m0 + wm * 32 + mi * 16 + (lane >> 2);
            int cc = n0 + wn * 64 + ni * 8 + (lane & 3) * 2;
            #pragma unroll
            for (int half = 0; half < 2; half++) {
                int rr = r + half * 8;
                float v0 = acc[mi][ni][half * 2];
                float v1 = acc[mi][ni][half * 2 + 1];
                size_t o = (size_t)rr * ldc + cc;
                if (EPI == 1) {
                    if (cc < NC)     atomicAdd(&C[o], v0);
                    if (cc + 1 < NC) atomicAdd(&C[o + 1], v1);
                } else {
                    *(float2*)(C + o) = make_float2(v0, v1);
                }
            }
        }
    }
}

// ---------------- dt_proj: softplus(xdbl[:, :64](fp32) @ W(bf16)^T + b) ----------------
// BM=128, BN=128, K=64 fixed. A converted fp32->bf16 in smem. grid (9,16).
__global__ void __launch_bounds__(256, 2)
dtproj_kernel(const float* __restrict__ xdbl,
              const __nv_bfloat16* __restrict__ W,
              const float* __restrict__ bias,
              float* __restrict__ C)
{
    __shared__ __align__(16) char sm[32768];   // A: 2 subtiles of 8K | B: 2 subtiles of 8K
    const uint32_t sb = smem_u32(sm);

    const int tid  = threadIdx.x;
    const int lane = tid & 31;
    const int wid  = tid >> 5;
    const int wm   = wid >> 1;
    const int wn   = wid & 1;
    const int m0   = blockIdx.x * 128;
    const int n0   = blockIdx.y * 128;

    // B via cp.async: subtile s (k in [32s,32s+32)), rows 128
    {
        int r = tid >> 2, ch = tid & 3;
        #pragma unroll
        for (int p = 0; p < 2; p++) {
            int rr = r + p * 64;
            #pragma unroll
            for (int s = 0; s < 2; s++) {
                cp16(sb + 16384 + s * 8192 + soff(rr, ch),
                     W + (size_t)(n0 + rr) * 64 + s * 32 + ch * 8);
            }
        }
        cp_commit();
    }
    // A: load fp32, convert, STS (thread t: row t>>1, k-half t&1)
    {
        int r = tid >> 1, half = tid & 1;
        const float* src = xdbl + (size_t)(m0 + r) * 96 + half * 32;
        uint32_t dst = sb + half * 8192;
        #pragma unroll
        for (int j = 0; j < 8; j++) {
            float4 v = *(const float4*)(src + j * 4);
            uint2 o;
            o.x = pack2(v.x, v.y);
            o.y = pack2(v.z, v.w);
            *(uint2*)(sm + (dst - sb) + soff(r, j >> 1) + (j & 1) * 8) = o;
        }
    }
    cp_wait<0>();
    __syncthreads();

    float acc[2][8][4];
    #pragma unroll
    for (int mi = 0; mi < 2; mi++)
        #pragma unroll
        for (int ni = 0; ni < 8; ni++)
            #pragma unroll
            for (int q = 0; q < 4; q++) acc[mi][ni][q] = 0.f;

    const int g  = lane >> 3;
    const int lr = lane & 7;

    #pragma unroll
    for (int ks = 0; ks < 4; ks++) {
        const int sub = ks >> 1;
        const int kc8 = (ks & 1) * 2;
        const uint32_t stA = sb + sub * 8192;
        const uint32_t stB = sb + 16384 + sub * 8192;
        uint32_t aH[2][4], bH[8][2];
        #pragma unroll
        for (int mi = 0; mi < 2; mi++) {
            int r  = wm * 32 + mi * 16 + (g & 1) * 8 + lr;
            int ch = kc8 + (g >> 1);
            LDSM4(aH[mi][0], aH[mi][1], aH[mi][2], aH[mi][3], stA + soff(r, ch));
        }
        #pragma unroll
        for (int t = 0; t < 4; t++) {
            int r  = wn * 64 + t * 16 + (g >> 1) * 8 + lr;
            int ch = kc8 + (g & 1);
            LDSM4(bH[2*t][0], bH[2*t][1], bH[2*t+1][0], bH[2*t+1][1], stB + soff(r, ch));
        }
        #pragma unroll
        for (int mi = 0; mi < 2; mi++)
            #pragma unroll
            for (int ni = 0; ni < 8; ni++) mma16816(acc[mi][ni], aH[mi], bH[ni]);
    }

    #pragma unroll
    for (int mi = 0; mi < 2; mi++) {
        #pragma unroll
        for (int ni = 0; ni < 8; ni++) {
            int r  = m0 + wm * 32 + mi * 16 + (lane >> 2);
            int cc = n0 + wn * 64 + ni * 8 + (lane & 3) * 2;
            #pragma unroll
            for (int half = 0; half < 2; half++) {
                int rr = r + half * 8;
                float v0 = softplusf(acc[mi][ni][half * 2]     + bias[cc]);
                float v1 = softplusf(acc[mi][ni][half * 2 + 1] + bias[cc + 1]);
                *(float2*)(C + (size_t)rr * DI_ + cc) = make_float2(v0, v1);
            }
        }
    }
}

// ---------------- fp32 split-K GEMM (prepend MLP only) ----------------
template<int BM, int BN, int BK, int TM, int TN>
__launch_bounds__((BM/TM)*(BN/TN), 2)
__global__ void gemm_f32(const float* __restrict__ Ap, int lda,
                         const float* __restrict__ Bp,
                         float* __restrict__ Cp,
                         int M, int N, int K) {
    constexpr int THREADS = (BM/TM)*(BN/TN);
    __shared__ float As[BK][BM];
    __shared__ float Bs[BK][BN];
    const int tid = threadIdx.x;
    const int tx  = tid % (BN/TN);
    const int ty  = tid / (BN/TN);
    const int m0  = blockIdx.x * BM;
    const int n0  = blockIdx.y * BN;
    int kl = K / gridDim.z;
    int kBeg = blockIdx.z * kl, kEnd = kBeg + kl;

    float acc[TM][TN];
    #pragma unroll
    for (int i = 0; i < TM; i++)
        #pragma unroll
        for (int j = 0; j < TN; j++) acc[i][j] = 0.f;

    for (int k0 = kBeg; k0 < kEnd; k0 += BK) {
        #pragma unroll
        for (int i = tid; i < BM*BK/4; i += THREADS) {
            int row = i / (BK/4);
            int kc  = (i % (BK/4)) * 4;
            float4 v = make_float4(0.f,0.f,0.f,0.f);
            if (m0 + row < M)
                v = *(const float4*)(Ap + (size_t)(m0+row)*lda + k0 + kc);
            As[kc+0][row] = v.x; As[kc+1][row] = v.y;
            As[kc+2][row] = v.z; As[kc+3][row] = v.w;
        }
        #pragma unroll
        for (int i = tid; i < BK*BN/4; i += THREADS) {
            int kr = i / (BN/4);
            int nc = (i % (BN/4)) * 4;
            float4 v = *(const float4*)(Bp + (size_t)(k0+kr)*N + n0 + nc);
            *(float4*)&Bs[kr][nc] = v;
        }
        __syncthreads();
        #pragma unroll
        for (int kk = 0; kk < BK; kk++) {
            float a[TM], b[TN];
            #pragma unroll
            for (int i = 0; i < TM; i += 4)
                *(float4*)&a[i] = *(const float4*)&As[kk][ty*TM + i];
            #pragma unroll
            for (int j = 0; j < TN; j += 4)
                *(float4*)&b[j] = *(const float4*)&Bs[kk][tx*TN + j];
            #pragma unroll
            for (int i = 0; i < TM; i++)
                #pragma unroll
                for (int j = 0; j < TN; j++)
                    acc[i][j] = fmaf(a[i], b[j], acc[i][j]);
        }
        __syncthreads();
    }
    #pragma unroll
    for (int i = 0; i < TM; i++) {
        int m = m0 + ty*TM + i;
        if (m >= M) continue;
        #pragma unroll
        for (int j = 0; j < TN; j++) {
            int n = n0 + tx*TN + j;
            atomicAdd(&Cp[(size_t)m*N + n], acc[i][j]);
        }
    }
}

// ---------------- merged convert + zero kernel ----------------
#define CW_N1 (L_*2*DI_*D_/4)       // 4194304
#define CW_N2 (L_*D_*DI_/4)         // 2097152
#define CW_N3 (L_*DI_*DR_/4)        // 131072
#define CW_N4 (L_*128*(DI_/4))      // 262144
#define CW_N5 (2*128*D_/4)          // 65536  (zero p1,p2)
#define CW_TOT (CW_N1+CW_N2+CW_N3+CW_N4+CW_N5)

__global__ void convert_all(const float* __restrict__ ipw, __nv_bfloat16* __restrict__ ipwh,
                            const float* __restrict__ opw, __nv_bfloat16* __restrict__ opwh,
                            const float* __restrict__ dtw, __nv_bfloat16* __restrict__ dtwh,
                            const float* __restrict__ xpw, __nv_bfloat16* __restrict__ xpwh,
                            float* __restrict__ p1, float* __restrict__ p2) {
    int i = blockIdx.x * 256 + threadIdx.x;
    if (i < CW_N1) {
        cvt_store4(((const float4*)ipw)[i], ipwh, i);
    } else if (i < CW_N1 + CW_N2) {
        int j = i - CW_N1;
        cvt_store4(((const float4*)opw)[j], opwh, j);
    } else if (i < CW_N1 + CW_N2 + CW_N3) {
        int j = i - (CW_N1 + CW_N2);
        cvt_store4(((const float4*)dtw)[j], dtwh, j);
    } else if (i < CW_N1 + CW_N2 + CW_N3 + CW_N4) {
        int j = i - (CW_N1 + CW_N2 + CW_N3);
        int k4   = j % (DI_/4);
        int nrow = (j / (DI_/4)) % 128;
        int lay  = j / (128 * (DI_/4));
        float4 v = make_float4(0.f, 0.f, 0.f, 0.f);
        if (nrow < 96)
            v = ((const float4*)xpw)[(size_t)(lay * 96 + nrow) * (DI_/4) + k4];
        cvt_store4(v, xpwh, j);
    } else if (i < CW_TOT) {
        int j = i - (CW_N1 + CW_N2 + CW_N3 + CW_N4);
        if (j < CW_N5/2) ((float4*)p1)[j] = make_float4(0.f,0.f,0.f,0.f);
        else             ((float4*)p2)[j - CW_N5/2] = make_float4(0.f,0.f,0.f,0.f);
    }
}

// ---------------- misc elementwise ----------------
__global__ void silu_kernel(float* __restrict__ p, int n) {
    int i = blockIdx.x * blockDim.x + threadIdx.x;
    if (i < n) p[i] = siluf(p[i]);
}

__global__ void build_h_kernel(const float* __restrict__ p,
                               const float* __restrict__ x,
                               float* __restrict__ h) {
    int idx = blockIdx.x * blockDim.x + threadIdx.x;
    if (idx >= M_*D_) return;
    int d = idx % D_;
    int m = idx / D_;
    int b = m / T_;
    int t = m % T_;
    h[idx] = (t < P_) ? p[(size_t)(b*P_ + t)*D_ + d]
                      : x[(size_t)(b*S_ + (t - P_))*D_ + d];
}

__global__ void rmsnorm_bf16_kernel(const float* __restrict__ in,
                                    const float* __restrict__ w,
                                    __nv_bfloat16* __restrict__ oh) {
    int row = blockIdx.x;
    int tid = threadIdx.x;
    const float4* r = (const float4*)(in + (size_t)row*D_);
    float4 x4 = r[tid];
    float s = x4.x*x4.x + x4.y*x4.y + x4.z*x4.z + x4.w*x4.w;
    #pragma unroll
    for (int o = 16; o; o >>= 1) s += __shfl_xor_sync(0xffffffffu, s, o);
    __shared__ float ws[8];
    __shared__ float scale_s;
    if ((tid & 31) == 0) ws[tid >> 5] = s;
    __syncthreads();
    if (tid == 0) {
        float t = 0.f;
        #pragma unroll
        for (int i = 0; i < 8; i++) t += ws[i];
        scale_s = rsqrtf(t / (float)D_ + 1e-5f);
    }
    __syncthreads();
    float sc = scale_s;
    float4 wv = ((const float4*)w)[tid];
    float4 v = make_float4(x4.x*sc*wv.x, x4.y*sc*wv.y, x4.z*sc*wv.z, x4.w*sc*wv.w);
    cvt_store4(v, oh, (size_t)row*(D_/4) + tid);
}

__global__ void final_kernel(const float* __restrict__ hin,
                             const float* __restrict__ w,
                             float* __restrict__ out) {
    int row = blockIdx.x;
    int b = row >> 9;
    int t = row & 511;
    int hrow = b*T_ + P_ + t;
    int tid = threadIdx.x;
    const float4* r = (const float4*)(hin + (size_t)hrow*D_);
    float4 x4 = r[tid];
    float s = x4.x*x4.x + x4.y*x4.y + x4.z*x4.z + x4.w*x4.w;
    #pragma unroll
    for (int o = 16; o; o >>= 1) s += __shfl_xor_sync(0xffffffffu, s, o);
    __shared__ float ws[8];
    __shared__ float scale_s;
    if ((tid & 31) == 0) ws[tid >> 5] = s;
    __syncthreads();
    if (tid == 0) {
        float tt = 0.f;
        #pragma unroll
        for (int i = 0; i < 8; i++) tt += ws[i];
        scale_s = rsqrtf(tt / (float)D_ + 1e-5f);
    }
    __syncthreads();
    float sc = scale_s;
    float4 wv = ((const float4*)w)[tid];
    float4 o4 = make_float4(x4.x*sc*wv.x, x4.y*sc*wv.y, x4.z*sc*wv.z, x4.w*sc*wv.w);
    ((float4*)(out + (size_t)row*D_))[tid] = o4;
}

// depthwise causal conv (DC=4) + silu, 4 channels/thread; zeroes xdbl
__global__ void conv_silu4(const float* __restrict__ xz,
                           const float* __restrict__ cw,
                           const float* __restrict__ cb,
                           float* __restrict__ xi,
                           __nv_bfloat16* __restrict__ xih,
                           float* __restrict__ xdbl) {
    int idx = blockIdx.x * blockDim.x + threadIdx.x;
    if (idx >= M_*(DI_/4)) return;
    if (idx < M_*96/4) ((float4*)xdbl)[idx] = make_float4(0.f,0.f,0.f,0.f);

    int e4 = idx % (DI_/4);
    int m  = idx / (DI_/4);
    int t  = m % T_;
    float4 w0 = ((const float4*)cw)[e4*4+0];
    float4 w1 = ((const float4*)cw)[e4*4+1];
    float4 w2 = ((const float4*)cw)[e4*4+2];
    float4 w3 = ((const float4*)cw)[e4*4+3];
    float4 acc = ((const float4*)cb)[e4];
    const float* wj[4] = { (const float*)&w0, (const float*)&w1,
                           (const float*)&w2, (const float*)&w3 };
    #pragma unroll
    for (int j = 0; j < 4; j++) {
        int tt = t - 3 + j;
        if (tt >= 0) {
            float4 xv = ((const float4*)(xz + (size_t)(m - 3 + j)*(2*DI_)))[e4];
            acc.x = fmaf(xv.x, wj[0][j], acc.x);
            acc.y = fmaf(xv.y, wj[1][j], acc.y);
            acc.z = fmaf(xv.z, wj[2][j], acc.z);
            acc.w = fmaf(xv.w, wj[3][j], acc.w);
        }
    }
    float4 v = make_float4(siluf(acc.x), siluf(acc.y), siluf(acc.z), siluf(acc.w));
    ((float4*)xi)[idx] = v;
    cvt_store4(v, xih, idx);
}

// selective scan: warp = 2 channels x 16 states; 8-timestep batches.
__global__ void scan_kernel(const float* __restrict__ xz,
                            const float* __restrict__ xi,
                            const float* __restrict__ xdbl,
                            const float* __restrict__ dt,
                            const float* __restrict__ A_log,
                            const float* __restrict__ Dp,
                            __nv_bfloat16* __restrict__ yh) {
    int lane = threadIdx.x & 31;
    int warp = threadIdx.x >> 5;
    int pair = blockIdx.x * 4 + warp;
    int b = pair >> 10;
    int e = ((pair & 1023) << 1) + (lane >> 4);
    int s = lane & 15;

    float A  = -expf(A_log[(size_t)e*DS_ + s]);
    float Dv = Dp[e];
    float h  = 0.f;
    int m0 = b * T_;

    const float* dt_p = dt   + (size_t)m0*DI_ + e;
    const float* xi_p = xi   + (size_t)m0*DI_ + e;
    const float* z_p  = xz   + (size_t)m0*(2*DI_) + DI_ + e;
    const float* bc_p = xdbl + (size_t)m0*96 + DR_ + s;
    size_t ybase = (size_t)m0*DI_ + (e & ~1);

    for (int tb = 0; tb < T_; tb += 8) {
        float dtv[8], xiv[8], Bv[8], Cv[8], zv[8];
        #pragma unroll
        for (int j = 0; j < 8; j++) {
            size_t t = tb + j;
            dtv[j] = dt_p[t*DI_];
            xiv[j] = xi_p[t*DI_];
            zv[j]  = z_p [t*(2*DI_)];
            Bv[j]  = bc_p[t*96];
            Cv[j]  = bc_p[t*96 + 16];
        }
        float p[8];
        #pragma unroll
        for (int j = 0; j < 8; j++) {
            float dA = __expf(dtv[j] * A);
            h = fmaf(dA, h, dtv[j] * Bv[j] * xiv[j]);
            p[j] = h * Cv[j];
        }
        #pragma unroll
        for (int o = 8; o >= 1; o >>= 1)
            #pragma unroll
            for (int j = 0; j < 8; j++)
                p[j] += __shfl_xor_sync(0xffffffffu, p[j], o);
        #pragma unroll
        for (int j = 0; j < 8; j++) {
            float val = (p[j] + xiv[j] * Dv) * siluf(zv[j]);
            float v1  = __shfl_down_sync(0xffffffffu, val, 16);
            if (lane == 0) {
                size_t o2 = (ybase + (size_t)(tb + j) * DI_) >> 1;
                ((uint32_t*)yh)[o2] = pack2(val, v1);
            }
        }
    }
}

// ---------------- host orchestration ----------------
extern "C" void kernel_launch(void* const* d_in, const int* in_sizes, int n_in,
                              void* d_out, int out_size) {
    (void)in_sizes; (void)n_in; (void)out_size;
    const float* x      = (const float*)d_in[0];
    const float* pc     = (const float*)d_in[1];
    const float* w1     = (const float*)d_in[2];
    const float* w2     = (const float*)d_in[3];
    const float* norm_w = (const float*)d_in[4];
    const float* ipw    = (const float*)d_in[5];
    const float* cw     = (const float*)d_in[6];
    const float* cb     = (const float*)d_in[7];
    const float* xpw    = (const float*)d_in[8];
    const float* dtw    = (const float*)d_in[9];
    const float* dtb    = (const float*)d_in[10];
    const float* A_log  = (const float*)d_in[11];
    const float* Dparam = (const float*)d_in[12];
    const float* opw    = (const float*)d_in[13];
    const float* fnw    = (const float*)d_in[14];

    float *h, *xzp, *xip, *dtp, *xdblp, *p1, *p2;
    cudaGetSymbolAddress((void**)&h,     g_h);
    cudaGetSymbolAddress((void**)&xzp,   g_xz);
    cudaGetSymbolAddress((void**)&xip,   g_xi);
    cudaGetSymbolAddress((void**)&dtp,   g_dt);
    cudaGetSymbolAddress((void**)&xdblp, g_xdbl);
    cudaGetSymbolAddress((void**)&p1,    g_p1);
    cudaGetSymbolAddress((void**)&p2,    g_p2);

    __nv_bfloat16 *xnh, *xih, *yh, *ipwh, *opwh, *xpwh, *dtwh;
    cudaGetSymbolAddress((void**)&xnh,  g_xn_h);
    cudaGetSymbolAddress((void**)&xih,  g_xi_h);
    cudaGetSymbolAddress((void**)&yh,   g_y_h);
    cudaGetSymbolAddress((void**)&ipwh, g_ipw_h);
    cudaGetSymbolAddress((void**)&opwh, g_opw_h);
    cudaGetSymbolAddress((void**)&xpwh, g_xpw_h);
    cudaGetSymbolAddress((void**)&dtwh, g_dtw_h);

    cudaFuncSetAttribute(tc_gemm<0>, cudaFuncAttributeMaxDynamicSharedMemorySize, GEMM_DYN);
    cudaFuncSetAttribute(tc_gemm<1>, cudaFuncAttributeMaxDynamicSharedMemorySize, GEMM_DYN);

    // ---- merged weight converts + zero p1/p2 (1 launch) ----
    convert_all<<<(CW_TOT+255)/256, 256>>>(ipw, ipwh, opw, opwh, dtw, dtwh, xpw, xpwh, p1, p2);

    // ---- prepend MLP: p = silu(pc @ w1) @ w2 (fp32 split-K) ----
    gemm_f32<64,64,16,4,4><<<dim3(2,16,6), 256>>>(pc, PCD_, w1, p1, 128, D_, PCD_);
    silu_kernel<<<(128*D_+255)/256, 256>>>(p1, 128*D_);
    gemm_f32<64,64,16,4,4><<<dim3(2,16,8), 256>>>(p1, D_, w2, p2, 128, D_, D_);
    build_h_kernel<<<(M_*D_+255)/256, 256>>>(p2, x, h);

    // ---- 4 mamba layers ----
    for (int l = 0; l < L_; l++) {
        rmsnorm_bf16_kernel<<<M_, 256>>>(h, norm_w + (size_t)l*D_, xnh);

        // xz = xn @ in_proj_w^T   [1152,1024] x [4096,1024]^T  (288 CTAs, 1 wave)
        tc_gemm<0><<<dim3(9, 32, 1), 256, GEMM_DYN>>>(
            xnh, ipwh + (size_t)l*2*DI_*D_, xzp, D_, 2*DI_, 2*DI_);

        conv_silu4<<<(M_*(DI_/4)+255)/256, 256>>>(
            xzp, cw + (size_t)l*DI_*4, cb + (size_t)l*DI_, xip, xih, xdblp);

        // xdbl = xi @ x_proj_w^T  [1152,2048] x [96(pad128),2048]^T  split-K=16 (144 CTAs)
        tc_gemm<1><<<dim3(9, 1, 16), 256, GEMM_DYN>>>(
            xih, xpwh + (size_t)l*128*DI_, xdblp, DI_, 96, 96);

        // dt = softplus(xdbl[:, :64] @ dt_proj_w^T + b)  fused A-convert (144 CTAs)
        dtproj_kernel<<<dim3(9, 16), 256>>>(
            xdblp, dtwh + (size_t)l*DI_*DR_, dtb + (size_t)l*DI_, dtp);

        // selective scan + gate -> y bf16
        scan_kernel<<<(B_*DI_/2)/4, 128>>>(
            xzp, xip, xdblp, dtp,
            A_log + (size_t)l*DI_*DS_, Dparam + (size_t)l*DI_, yh);

        // h += y @ out_proj_w^T   [1152,2048] x [1024,2048]^T  split-K=2 (144 CTAs)
        tc_gemm<1><<<dim3(9, 8, 2), 256, GEMM_DYN>>>(
            yh, opwh + (size_t)l*D_*DI_, h, DI_, D_, D_);
    }

    // ---- final rmsnorm + slice ----
    final_kernel<<<B_*S_, 256>>>(h, fnw, (float*)d_out);
}